// round 10
// baseline (speedup 1.0000x reference)
#include <cuda_runtime.h>
#include <cstdint>
#include <math.h>

// B=4096 R=130 T=200 Q=64
__device__ float g_qky[(size_t)4096 * 130 * 80];   // qk(64) | y1(16)
__device__ float g_rel[(size_t)4096 * 130 * 130];  // rel raw -> A in place
__device__ float g_z[(size_t)4096 * 130 * 16];     // pre-BN z (stride 16)
__device__ float g_h[(size_t)4096 * 130 * 16];     // h_i (stride 16)
__device__ float g_stats[7][2][130];               // (sum, sumsq) per channel
__device__ float2 g_ss[7][130];                    // (scale, shift)

__device__ __forceinline__ void ffma2(unsigned long long& d, unsigned long long a,
                                      unsigned long long b) {
    asm("fma.rn.f32x2 %0, %1, %2, %0;" : "+l"(d) : "l"(a), "l"(b));
}
__device__ __forceinline__ float2 u2f(unsigned long long u) {
    float2 f; asm("mov.b64 {%0, %1}, %2;" : "=f"(f.x), "=f"(f.y) : "l"(u)); return f;
}

__global__ void k_zero() {
    float* p = &g_stats[0][0][0];
    for (int i = threadIdx.x; i < 7 * 2 * 130; i += 256) p[i] = 0.f;
}

// C[m,n] = sum_t clean(X)[m,t] * W[n,t] + bias   (W = [wq;w1], M=B*R, N=80, K=200)
__global__ void __launch_bounds__(256) k_gemm0(const float* __restrict__ X,
        const float* __restrict__ wq, const float* __restrict__ bq,
        const float* __restrict__ w1, const float* __restrict__ b1) {
    extern __shared__ float sm[];
    float* Xs = sm;                // 128 x 102
    float* Ws = sm + 128 * 102;    // 80 x 102
    const int tid = threadIdx.x;
    const int tx = tid & 15, ty = tid >> 4;
    const size_t m0 = (size_t)blockIdx.x * 128;
    unsigned long long acc[8][5];
#pragma unroll
    for (int i = 0; i < 8; i++)
#pragma unroll
        for (int j = 0; j < 5; j++) acc[i][j] = 0ull;

    for (int kc = 0; kc < 2; kc++) {
        for (int i = tid; i < 128 * 50; i += 256) {
            int r = i / 50, c = (i % 50) * 2;
            float2 v = *(const float2*)(X + (m0 + r) * 200 + kc * 100 + c);
            if (!(v.x == v.x)) v.x = 0.f;
            if (!(v.y == v.y)) v.y = 0.f;
            *(float2*)(Xs + r * 102 + c) = v;
        }
        for (int i = tid; i < 80 * 50; i += 256) {
            int r = i / 50, c = (i % 50) * 2;
            const float* src = (r < 64) ? wq + r * 200 : w1 + (r - 64) * 200;
            *(float2*)(Ws + r * 102 + c) = *(const float2*)(src + kc * 100 + c);
        }
        __syncthreads();
#pragma unroll 5
        for (int kk = 0; kk < 50; kk++) {
            unsigned long long xv[8], wv[5];
#pragma unroll
            for (int i = 0; i < 8; i++)
                xv[i] = *(const unsigned long long*)(Xs + (ty * 8 + i) * 102 + 2 * kk);
#pragma unroll
            for (int j = 0; j < 5; j++)
                wv[j] = *(const unsigned long long*)(Ws + (tx * 5 + j) * 102 + 2 * kk);
#pragma unroll
            for (int i = 0; i < 8; i++)
#pragma unroll
                for (int j = 0; j < 5; j++) ffma2(acc[i][j], xv[i], wv[j]);
        }
        __syncthreads();
    }
#pragma unroll
    for (int j = 0; j < 5; j++) {
        int n = tx * 5 + j;
        float bias = (n < 64) ? bq[n] : b1[n - 64];
#pragma unroll
        for (int i = 0; i < 8; i++) {
            float2 f = u2f(acc[i][j]);
            g_qky[(m0 + ty * 8 + i) * 80 + n] = f.x + f.y + bias;
        }
    }
}

// rel[b,r,s] = sum_q qk[b,r,q] * flat[b, q*130+s];  accumulate BN0 stats
__global__ void __launch_bounds__(256) k_rel() {
    __shared__ float buf[130 * 64];
    __shared__ float ssum[130], ssq[130];
    const int b = blockIdx.x, tid = threadIdx.x;
    const float* qk = g_qky + (size_t)b * 130 * 80;
    for (int i = tid; i < 130 * 64; i += 256) buf[i] = qk[(i >> 6) * 80 + (i & 63)];
    for (int i = tid; i < 130; i += 256) { ssum[i] = 0.f; ssq[i] = 0.f; }
    __syncthreads();
    float* out = g_rel + (size_t)b * 16900;
    for (int g = tid; g < 676; g += 256) {
        int r0 = (g / 26) * 5, s0 = (g % 26) * 5;
        float acc[5][5];
#pragma unroll
        for (int i = 0; i < 5; i++)
#pragma unroll
            for (int j = 0; j < 5; j++) acc[i][j] = 0.f;
        for (int q = 0; q < 64; q++) {
            float kv[5];
#pragma unroll
            for (int j = 0; j < 5; j++) kv[j] = buf[q * 130 + s0 + j];
#pragma unroll
            for (int i = 0; i < 5; i++) {
                float a = buf[(r0 + i) * 64 + q];
#pragma unroll
                for (int j = 0; j < 5; j++) acc[i][j] += a * kv[j];
            }
        }
#pragma unroll
        for (int i = 0; i < 5; i++) {
            float s = 0.f, s2 = 0.f;
#pragma unroll
            for (int j = 0; j < 5; j++) {
                float v = acc[i][j];
                out[(r0 + i) * 130 + s0 + j] = v;
                s += v; s2 += v * v;
            }
            atomicAdd(&ssum[r0 + i], s);
            atomicAdd(&ssq[r0 + i], s2);
        }
    }
    __syncthreads();
    if (tid < 130) {
        atomicAdd(&g_stats[0][0][tid], ssum[tid]);
        atomicAdd(&g_stats[0][1][tid], ssq[tid]);
    }
}

__global__ void k_fin(int slot, float cinv, const float* __restrict__ g,
                      const float* __restrict__ be) {
    int r = threadIdx.x;
    if (r < 130) {
        float m = g_stats[slot][0][r] * cinv;
        float v = g_stats[slot][1][r] * cinv - m * m;
        float sc = g[r] * rsqrtf(v + 1e-5f);
        g_ss[slot][r] = make_float2(sc, be[r] - sc * m);
    }
}

// BN0 + softmax + relu(-thr) -> A (writeback), z1 = A @ y1, BN1 stats
__global__ void __launch_bounds__(256) k_adjL1(const float* __restrict__ thr_p) {
    extern __shared__ float sm[];
    float* As = sm;               // 130 x 131
    float* ys = sm + 130 * 131;   // 130 x 16
    __shared__ float ssum[130], ssq[130];
    const int b = blockIdx.x, tid = threadIdx.x;
    const float thr = *thr_p;
    float* rel = g_rel + (size_t)b * 16900;
    for (int i = tid; i < 16900; i += 256) {
        int r = i / 130, s = i - r * 130;
        float2 ss = g_ss[0][r];
        As[r * 131 + s] = ss.x * rel[i] + ss.y;
    }
    for (int i = tid; i < 130 * 16; i += 256)
        ys[i] = g_qky[((size_t)b * 130 + (i >> 4)) * 80 + 64 + (i & 15)];
    if (tid < 130) { ssum[tid] = 0.f; ssq[tid] = 0.f; }
    __syncthreads();
    const int w = tid >> 5, lane = tid & 31;
    for (int r = w; r < 130; r += 8) {
        float mx = -1e30f;
        for (int s = lane; s < 130; s += 32) mx = fmaxf(mx, As[r * 131 + s]);
#pragma unroll
        for (int o = 16; o; o >>= 1) mx = fmaxf(mx, __shfl_xor_sync(~0u, mx, o));
        float sum = 0.f;
        for (int s = lane; s < 130; s += 32) {
            float e = __expf(As[r * 131 + s] - mx);
            As[r * 131 + s] = e;
            sum += e;
        }
#pragma unroll
        for (int o = 16; o; o >>= 1) sum += __shfl_xor_sync(~0u, sum, o);
        float inv = 1.f / sum;
        for (int s = lane; s < 130; s += 32) {
            float a = fmaxf(As[r * 131 + s] * inv - thr, 0.f);
            As[r * 131 + s] = a;
            rel[r * 130 + s] = a;
        }
    }
    __syncthreads();
    for (int o = tid; o < 2080; o += 256) {
        int r = o >> 4, f = o & 15;
        float acc = 0.f;
        for (int s = 0; s < 130; s++) acc += As[r * 131 + s] * ys[s * 16 + f];
        g_z[((size_t)b * 130 + r) * 16 + f] = acc;
        atomicAdd(&ssum[r], acc);
        atomicAdd(&ssq[r], acc * acc);
    }
    __syncthreads();
    if (tid < 130) {
        atomicAdd(&g_stats[1][0][tid], ssum[tid]);
        atomicAdd(&g_stats[1][1][tid], ssq[tid]);
    }
}

// h = relu(bn_{SLOT-1}(z)) [+res from g_h]; write g_h; y = h@w^T+b; z = A@y; stats[SLOT]
template <int FIN, int FOUT, bool RES, int SLOT>
__global__ void __launch_bounds__(256) k_layer(const float* __restrict__ w,
                                               const float* __restrict__ bias) {
    extern __shared__ float sm[];
    float* As = sm;                 // 130 x 131
    float* hs = sm + 130 * 131;     // 130 x FIN
    float* ys = hs + 130 * FIN;     // 130 x FOUT
    __shared__ float ws[FOUT * FIN], bs_[FOUT];
    __shared__ float ssum[130], ssq[130];
    const int b = blockIdx.x, tid = threadIdx.x;
    const float* rel = g_rel + (size_t)b * 16900;
    for (int i = tid; i < 16900; i += 256) {
        int r = i / 130;
        As[r * 131 + (i - r * 130)] = rel[i];
    }
    if (tid < FOUT * FIN) ws[tid] = w[tid];
    if (tid < FOUT) bs_[tid] = bias[tid];
    if (tid < 130) { ssum[tid] = 0.f; ssq[tid] = 0.f; }
    for (int i = tid; i < 130 * FIN; i += 256) {
        int r = i / FIN, f = i - r * FIN;
        size_t gi = ((size_t)b * 130 + r) * 16 + f;
        float2 ss = g_ss[SLOT - 1][r];
        float hv = fmaxf(ss.x * g_z[gi] + ss.y, 0.f);
        if (RES) hv += g_h[gi];
        hs[i] = hv;
        g_h[gi] = hv;
    }
    __syncthreads();
    for (int o = tid; o < 130 * FOUT; o += 256) {
        int r = o / FOUT, fo = o - r * FOUT;
        float acc = bs_[fo];
#pragma unroll
        for (int f = 0; f < FIN; f++) acc += hs[r * FIN + f] * ws[fo * FIN + f];
        ys[o] = acc;
    }
    __syncthreads();
    for (int o = tid; o < 130 * FOUT; o += 256) {
        int r = o / FOUT, fo = o - r * FOUT;
        float acc = 0.f;
        for (int s = 0; s < 130; s++) acc += As[r * 131 + s] * ys[s * FOUT + fo];
        g_z[((size_t)b * 130 + r) * 16 + fo] = acc;
        atomicAdd(&ssum[r], acc);
        atomicAdd(&ssq[r], acc * acc);
    }
    __syncthreads();
    if (tid < 130) {
        atomicAdd(&g_stats[SLOT][0][tid], ssum[tid]);
        atomicAdd(&g_stats[SLOT][1][tid], ssq[tid]);
    }
}

// h6 = relu(bn6(z6)) + h5; out = relu(flat(h6) @ w_mlp^T + b_mlp)
__global__ void __launch_bounds__(128) k_mlp(const float* __restrict__ wm,
                                             const float* __restrict__ bm,
                                             float* __restrict__ out) {
    __shared__ float red[2][4];
    const int b = blockIdx.x, tid = threadIdx.x;
    float a0 = 0.f, a1 = 0.f;
    for (int i = tid; i < 260; i += 128) {
        int r = i >> 1, f = i & 1;
        size_t gi = ((size_t)b * 130 + r) * 16 + f;
        float2 ss = g_ss[6][r];
        float hv = fmaxf(ss.x * g_z[gi] + ss.y, 0.f) + g_h[gi];
        a0 += hv * wm[i];
        a1 += hv * wm[260 + i];
    }
#pragma unroll
    for (int o = 16; o; o >>= 1) {
        a0 += __shfl_xor_sync(~0u, a0, o);
        a1 += __shfl_xor_sync(~0u, a1, o);
    }
    if ((tid & 31) == 0) { red[0][tid >> 5] = a0; red[1][tid >> 5] = a1; }
    __syncthreads();
    if (tid == 0) {
        float r0 = red[0][0] + red[0][1] + red[0][2] + red[0][3];
        float r1 = red[1][0] + red[1][1] + red[1][2] + red[1][3];
        out[b * 2 + 0] = fmaxf(r0 + bm[0], 0.f);
        out[b * 2 + 1] = fmaxf(r1 + bm[1], 0.f);
    }
}

extern "C" void kernel_launch(void* const* d_in, const int* in_sizes, int n_in,
                              void* d_out, int out_size) {
    (void)in_sizes; (void)n_in; (void)out_size;
    const float* X   = (const float*)d_in[0];
    const float* thr = (const float*)d_in[1];
    const float* wq  = (const float*)d_in[2];
    const float* bq  = (const float*)d_in[3];
    const float* g_t = (const float*)d_in[4];
    const float* b_t = (const float*)d_in[5];
    const float *w1 = (const float*)d_in[6],  *b1 = (const float*)d_in[7];
    const float *g1 = (const float*)d_in[8],  *e1 = (const float*)d_in[9];
    const float *w2 = (const float*)d_in[10], *b2 = (const float*)d_in[11];
    const float *g2 = (const float*)d_in[12], *e2 = (const float*)d_in[13];
    const float *w3 = (const float*)d_in[14], *b3 = (const float*)d_in[15];
    const float *g3 = (const float*)d_in[16], *e3 = (const float*)d_in[17];
    const float *w4 = (const float*)d_in[18], *b4 = (const float*)d_in[19];
    const float *g4 = (const float*)d_in[20], *e4 = (const float*)d_in[21];
    const float *w5 = (const float*)d_in[22], *b5 = (const float*)d_in[23];
    const float *g5 = (const float*)d_in[24], *e5 = (const float*)d_in[25];
    const float *w6 = (const float*)d_in[26], *b6 = (const float*)d_in[27];
    const float *g6 = (const float*)d_in[28], *e6 = (const float*)d_in[29];
    const float *wm = (const float*)d_in[30], *bm = (const float*)d_in[31];

    const int sm0  = (128 * 102 + 80 * 102) * 4;            // 84864
    const int smA  = (130 * 131 + 130 * 16) * 4;            // 76440
    const int smL2 = (130 * 131 + 130 * 16 + 130 * 16) * 4; // 84760
    const int smL3 = (130 * 131 + 130 * 16 + 130 * 4) * 4;
    const int smL4 = (130 * 131 + 130 * 4 + 130 * 4) * 4;
    const int smL5 = (130 * 131 + 130 * 4 + 130 * 2) * 4;
    const int smL6 = (130 * 131 + 130 * 2 + 130 * 2) * 4;
    cudaFuncSetAttribute(k_gemm0, cudaFuncAttributeMaxDynamicSharedMemorySize, sm0);
    cudaFuncSetAttribute(k_adjL1, cudaFuncAttributeMaxDynamicSharedMemorySize, smA);
    cudaFuncSetAttribute(k_layer<16,16,false,2>, cudaFuncAttributeMaxDynamicSharedMemorySize, smL2);
    cudaFuncSetAttribute(k_layer<16,4,true,3>,  cudaFuncAttributeMaxDynamicSharedMemorySize, smL3);
    cudaFuncSetAttribute(k_layer<4,4,false,4>,  cudaFuncAttributeMaxDynamicSharedMemorySize, smL4);
    cudaFuncSetAttribute(k_layer<4,2,true,5>,   cudaFuncAttributeMaxDynamicSharedMemorySize, smL5);
    cudaFuncSetAttribute(k_layer<2,2,false,6>,  cudaFuncAttributeMaxDynamicSharedMemorySize, smL6);

    k_zero<<<1, 256>>>();
    k_gemm0<<<4160, 256, sm0>>>(X, wq, bq, w1, b1);
    k_rel<<<4096, 256>>>();
    k_fin<<<1, 160>>>(0, 1.f / (4096.f * 130.f), g_t, b_t);
    k_adjL1<<<4096, 256, smA>>>(thr);
    k_fin<<<1, 160>>>(1, 1.f / 65536.f, g1, e1);
    k_layer<16,16,false,2><<<4096, 256, smL2>>>(w2, b2);
    k_fin<<<1, 160>>>(2, 1.f / 65536.f, g2, e2);
    k_layer<16,4,true,3><<<4096, 256, smL3>>>(w3, b3);
    k_fin<<<1, 160>>>(3, 1.f / 16384.f, g3, e3);
    k_layer<4,4,false,4><<<4096, 256, smL4>>>(w4, b4);
    k_fin<<<1, 160>>>(4, 1.f / 16384.f, g4, e4);
    k_layer<4,2,true,5><<<4096, 256, smL5>>>(w5, b5);
    k_fin<<<1, 160>>>(5, 1.f / 8192.f, g5, e5);
    k_layer<2,2,false,6><<<4096, 256, smL6>>>(w6, b6);
    k_fin<<<1, 160>>>(6, 1.f / 8192.f, g6, e6);
    k_mlp<<<4096, 128>>>(wm, bm, (float*)d_out);
}

// round 12
// speedup vs baseline: 1.5862x; 1.5862x over previous
#include <cuda_runtime.h>
#include <cstdint>
#include <math.h>

typedef unsigned long long ULL;

// B=4096 R=130 T=200 Q=64
__device__ float g_qky[(size_t)4096 * 130 * 80];   // qk(64) | y1(16), stride 80
__device__ float g_rel[(size_t)4096 * 130 * 130];  // rel raw -> A in place
__device__ float g_z[(size_t)4096 * 130 * 16];     // pre-BN z (stride 16)
__device__ float g_h[(size_t)4096 * 130 * 16];     // h_i (stride 16)
__device__ float g_stats[7][2][130];               // (sum, sumsq) per channel

__device__ __forceinline__ void ffma2(ULL& d, ULL a, ULL b) {
    asm("fma.rn.f32x2 %0, %1, %2, %0;" : "+l"(d) : "l"(a), "l"(b));
}
__device__ __forceinline__ ULL pack2(float v) {
    ULL r; asm("mov.b64 %0, {%1, %1};" : "=l"(r) : "f"(v)); return r;
}
__device__ __forceinline__ float2 u2f(ULL u) {
    float2 f; asm("mov.b64 {%0, %1}, %2;" : "=f"(f.x), "=f"(f.y) : "l"(u)); return f;
}
__device__ __forceinline__ void cpa16(void* dst, const void* src) {
    unsigned d = (unsigned)__cvta_generic_to_shared(dst);
    asm volatile("cp.async.cg.shared.global [%0], [%1], 16;" :: "r"(d), "l"(src));
}
__device__ __forceinline__ void cpwait() {
    asm volatile("cp.async.wait_all;" ::: "memory");
}

__global__ void k_zero() {
    float* p = &g_stats[0][0][0];
    for (int i = threadIdx.x; i < 7 * 2 * 130; i += 256) p[i] = 0.f;
}

// C[m,n] = sum_t clean(X)[m,t] * W[n,t] + bias   (W=[wq;w1], M=B*R, N=80, K=200)
__global__ void __launch_bounds__(256) k_gemm0(const float* __restrict__ X,
        const float* __restrict__ wq, const float* __restrict__ bq,
        const float* __restrict__ w1, const float* __restrict__ b1) {
    extern __shared__ float sm[];
    float* Xs = sm;                // 128 x 102
    float* Ws = sm + 128 * 102;    // 80 x 102
    const int tid = threadIdx.x;
    const int tx = tid & 15, ty = tid >> 4;
    const size_t m0 = (size_t)blockIdx.x * 128;
    ULL acc[8][5];
#pragma unroll
    for (int i = 0; i < 8; i++)
#pragma unroll
        for (int j = 0; j < 5; j++) acc[i][j] = 0ull;

    for (int kc = 0; kc < 2; kc++) {
        for (int i = tid; i < 128 * 50; i += 256) {
            int r = i / 50, c = (i % 50) * 2;
            float2 v = *(const float2*)(X + (m0 + r) * 200 + kc * 100 + c);
            if (!(v.x == v.x)) v.x = 0.f;
            if (!(v.y == v.y)) v.y = 0.f;
            *(float2*)(Xs + r * 102 + c) = v;
        }
        for (int i = tid; i < 80 * 50; i += 256) {
            int r = i / 50, c = (i % 50) * 2;
            const float* src = (r < 64) ? wq + r * 200 : w1 + (r - 64) * 200;
            *(float2*)(Ws + r * 102 + c) = *(const float2*)(src + kc * 100 + c);
        }
        __syncthreads();
#pragma unroll 5
        for (int kk = 0; kk < 50; kk++) {
            ULL xv[8], wv[5];
#pragma unroll
            for (int i = 0; i < 8; i++)
                xv[i] = *(const ULL*)(Xs + (ty * 8 + i) * 102 + 2 * kk);
#pragma unroll
            for (int j = 0; j < 5; j++)
                wv[j] = *(const ULL*)(Ws + (tx * 5 + j) * 102 + 2 * kk);
#pragma unroll
            for (int i = 0; i < 8; i++)
#pragma unroll
                for (int j = 0; j < 5; j++) ffma2(acc[i][j], xv[i], wv[j]);
        }
        __syncthreads();
    }
#pragma unroll
    for (int j = 0; j < 5; j++) {
        int n = tx * 5 + j;
        float bias = (n < 64) ? bq[n] : b1[n - 64];
#pragma unroll
        for (int i = 0; i < 8; i++) {
            float2 f = u2f(acc[i][j]);
            g_qky[(m0 + ty * 8 + i) * 80 + n] = f.x + f.y + bias;
        }
    }
}

// rel[b,r,s] = sum_q qk[b,r,q] * flat[b, q*130+s]; 5x10 f32x2 tiles; BN0 stats
__global__ void __launch_bounds__(352) k_rel() {
    __shared__ float ba[130 * 64];     // qk row-major
    __shared__ float bk[64 * 132];     // flat reshaped, padded
    __shared__ float ssum[130], ssq[130];
    const int b = blockIdx.x, tid = threadIdx.x;
    const float* qk = g_qky + (size_t)b * 10400;
    for (int f = tid; f < 8320; f += 352) {
        float v = qk[(f >> 6) * 80 + (f & 63)];
        ba[f] = v;
        bk[(f / 130) * 132 + (f % 130)] = v;
    }
    if (tid < 130) { ssum[tid] = 0.f; ssq[tid] = 0.f; }
    __syncthreads();
    float* out = g_rel + (size_t)b * 16900;
    if (tid < 338) {
        const int tr = tid / 13, ts = tid - tr * 13;
        const int r0 = tr * 5, s0 = ts * 10;
        ULL acc[5][5];
#pragma unroll
        for (int i = 0; i < 5; i++)
#pragma unroll
            for (int j = 0; j < 5; j++) acc[i][j] = 0ull;
        for (int q = 0; q < 64; q++) {
            ULL kv[5];
#pragma unroll
            for (int j = 0; j < 5; j++) kv[j] = *(const ULL*)(bk + q * 132 + s0 + 2 * j);
#pragma unroll
            for (int i = 0; i < 5; i++) {
                ULL ap = pack2(ba[(r0 + i) * 64 + q]);
#pragma unroll
                for (int j = 0; j < 5; j++) ffma2(acc[i][j], ap, kv[j]);
            }
        }
#pragma unroll
        for (int i = 0; i < 5; i++) {
            float s = 0.f, s2 = 0.f;
#pragma unroll
            for (int j = 0; j < 5; j++) {
                float2 f = u2f(acc[i][j]);
                *(float2*)(out + (r0 + i) * 130 + s0 + 2 * j) = f;
                s += f.x + f.y; s2 += f.x * f.x + f.y * f.y;
            }
            atomicAdd(&ssum[r0 + i], s);
            atomicAdd(&ssq[r0 + i], s2);
        }
    }
    __syncthreads();
    if (tid < 130) {
        atomicAdd(&g_stats[0][0][tid], ssum[tid]);
        atomicAdd(&g_stats[0][1][tid], ssq[tid]);
    }
}

// BN0 + softmax + relu(-thr) -> A, z1 = A @ y1 (f32x2 tiled), BN1 stats
__global__ void __launch_bounds__(256) k_adjL1(const float* __restrict__ thr_p,
        const float* __restrict__ gam, const float* __restrict__ bet) {
    extern __shared__ float sm[];
    float* As = sm;            // 130 x 130
    float* ys = sm + 16900;    // 130 x 16
    __shared__ float2 sss[130];
    __shared__ float ssum[130], ssq[130];
    const int b = blockIdx.x, tid = threadIdx.x;
    const float thr = *thr_p;
    float* rel = g_rel + (size_t)b * 16900;
    if (tid < 130) {
        const float cinv = 1.f / 532480.f;
        float m = g_stats[0][0][tid] * cinv;
        float v = g_stats[0][1][tid] * cinv - m * m;
        float sc = gam[tid] * rsqrtf(v + 1e-5f);
        sss[tid] = make_float2(sc, bet[tid] - sc * m);
        ssum[tid] = 0.f; ssq[tid] = 0.f;
    }
    for (int i = tid; i < 2080; i += 256)
        ys[i] = g_qky[(size_t)b * 10400 + (i >> 4) * 80 + 64 + (i & 15)];
    __syncthreads();
    for (int i2 = tid; i2 < 8450; i2 += 256) {
        int r = i2 / 65;
        float2 ss = sss[r];
        float2 v = *(const float2*)(rel + 2 * i2);
        v.x = ss.x * v.x + ss.y;
        v.y = ss.x * v.y + ss.y;
        *(float2*)(As + 2 * i2) = v;
    }
    __syncthreads();
    const int w = tid >> 5, lane = tid & 31;
    for (int r = w; r < 130; r += 8) {
        float mx = -1e30f;
        for (int s = lane; s < 130; s += 32) mx = fmaxf(mx, As[r * 130 + s]);
#pragma unroll
        for (int o = 16; o; o >>= 1) mx = fmaxf(mx, __shfl_xor_sync(~0u, mx, o));
        float sum = 0.f;
        for (int s = lane; s < 130; s += 32) {
            float e = __expf(As[r * 130 + s] - mx);
            As[r * 130 + s] = e;
            sum += e;
        }
#pragma unroll
        for (int o = 16; o; o >>= 1) sum += __shfl_xor_sync(~0u, sum, o);
        float inv = 1.f / sum;
        for (int s = lane; s < 130; s += 32) {
            float a = fmaxf(As[r * 130 + s] * inv - thr, 0.f);
            As[r * 130 + s] = a;
            rel[r * 130 + s] = a;
        }
    }
    __syncthreads();
    for (int g = tid; g < 260; g += 256) {
        int r = g >> 1, cg = g & 1;
        const float* yp = ys + cg * 8;
        ULL a0 = 0, a1 = 0, a2 = 0, a3 = 0;
        for (int s = 0; s < 130; s++) {
            ULL ap = pack2(As[r * 130 + s]);
            ulonglong2 p = *(const ulonglong2*)(yp + s * 16);
            ulonglong2 q = *(const ulonglong2*)(yp + s * 16 + 4);
            ffma2(a0, ap, p.x); ffma2(a1, ap, p.y);
            ffma2(a2, ap, q.x); ffma2(a3, ap, q.y);
        }
        float2 f0 = u2f(a0), f1 = u2f(a1), f2 = u2f(a2), f3 = u2f(a3);
        float* zp = g_z + (size_t)b * 2080 + r * 16 + cg * 8;
        *(float4*)zp = make_float4(f0.x, f0.y, f1.x, f1.y);
        *(float4*)(zp + 4) = make_float4(f2.x, f2.y, f3.x, f3.y);
        float s1 = f0.x + f0.y + f1.x + f1.y + f2.x + f2.y + f3.x + f3.y;
        float s2 = f0.x * f0.x + f0.y * f0.y + f1.x * f1.x + f1.y * f1.y
                 + f2.x * f2.x + f2.y * f2.y + f3.x * f3.x + f3.y * f3.y;
        atomicAdd(&ssum[r], s1);
        atomicAdd(&ssq[r], s2);
    }
    __syncthreads();
    if (tid < 130) {
        atomicAdd(&g_stats[1][0][tid], ssum[tid]);
        atomicAdd(&g_stats[1][1][tid], ssq[tid]);
    }
}

// h = relu(bn_{SLOT-1}(z)) [+res]; g_h = h; y = h@w^T+b; z = A@y; stats[SLOT]
template <int FIN, int FOUT, bool RES, int SLOT>
__global__ void __launch_bounds__(256) k_layer(const float* __restrict__ w,
        const float* __restrict__ bias, const float* __restrict__ gam,
        const float* __restrict__ bet, float cinv) {
    extern __shared__ float sm[];
    float* As = sm;                    // 130*130
    float* hs = sm + 16900;            // 130*FIN
    float* ys = hs + 130 * FIN;        // 130*FOUT
    __shared__ float ws[FOUT * FIN], bs_[FOUT];
    __shared__ float2 sss[130];
    __shared__ float ssum[130], ssq[130];
    const int b = blockIdx.x, tid = threadIdx.x;
    const float* rel = g_rel + (size_t)b * 16900;
    for (int i4 = tid; i4 < 4225; i4 += 256)
        cpa16(As + 4 * i4, rel + 4 * i4);
    if (tid < FOUT * FIN) ws[tid] = w[tid];
    if (tid < FOUT) bs_[tid] = bias[tid];
    if (tid < 130) {
        float m = g_stats[SLOT - 1][0][tid] * cinv;
        float v = g_stats[SLOT - 1][1][tid] * cinv - m * m;
        float sc = gam[tid] * rsqrtf(v + 1e-5f);
        sss[tid] = make_float2(sc, bet[tid] - sc * m);
        ssum[tid] = 0.f; ssq[tid] = 0.f;
    }
    __syncthreads();
    const size_t base = (size_t)b * 2080;
    if (FIN == 16) {
        for (int i4 = tid; i4 < 520; i4 += 256) {
            int r = i4 >> 2;
            float2 ss = sss[r];
            float4 z = *(const float4*)(g_z + base + 4 * i4);
            float4 h4;
            h4.x = fmaxf(ss.x * z.x + ss.y, 0.f);
            h4.y = fmaxf(ss.x * z.y + ss.y, 0.f);
            h4.z = fmaxf(ss.x * z.z + ss.y, 0.f);
            h4.w = fmaxf(ss.x * z.w + ss.y, 0.f);
            if (RES) {
                float4 p = *(const float4*)(g_h + base + 4 * i4);
                h4.x += p.x; h4.y += p.y; h4.z += p.z; h4.w += p.w;
            }
            *(float4*)(hs + 4 * i4) = h4;
            *(float4*)(g_h + base + 4 * i4) = h4;
        }
    } else if (FIN == 4) {
        if (tid < 130) {
            float2 ss = sss[tid];
            float4 z = *(const float4*)(g_z + base + tid * 16);
            float4 h4;
            h4.x = fmaxf(ss.x * z.x + ss.y, 0.f);
            h4.y = fmaxf(ss.x * z.y + ss.y, 0.f);
            h4.z = fmaxf(ss.x * z.z + ss.y, 0.f);
            h4.w = fmaxf(ss.x * z.w + ss.y, 0.f);
            if (RES) {
                float4 p = *(const float4*)(g_h + base + tid * 16);
                h4.x += p.x; h4.y += p.y; h4.z += p.z; h4.w += p.w;
            }
            *(float4*)(hs + tid * 4) = h4;
            *(float4*)(g_h + base + tid * 16) = h4;
        }
    } else {  // FIN == 2
        if (tid < 130) {
            float2 ss = sss[tid];
            float2 z = *(const float2*)(g_z + base + tid * 16);
            float2 h2;
            h2.x = fmaxf(ss.x * z.x + ss.y, 0.f);
            h2.y = fmaxf(ss.x * z.y + ss.y, 0.f);
            if (RES) {
                float2 p = *(const float2*)(g_h + base + tid * 16);
                h2.x += p.x; h2.y += p.y;
            }
            *(float2*)(hs + tid * 2) = h2;
            *(float2*)(g_h + base + tid * 16) = h2;
        }
    }
    __syncthreads();
    for (int o = tid; o < 130 * FOUT; o += 256) {
        int r = o / FOUT, fo = o % FOUT;
        float acc = bs_[fo];
#pragma unroll
        for (int f = 0; f < FIN; f++) acc += hs[r * FIN + f] * ws[fo * FIN + f];
        ys[o] = acc;
    }
    cpwait();
    __syncthreads();
    if (FOUT == 16) {
        for (int g = tid; g < 260; g += 256) {
            int r = g >> 1, cg = g & 1;
            const float* yp = ys + cg * 8;
            ULL a0 = 0, a1 = 0, a2 = 0, a3 = 0;
            for (int s = 0; s < 130; s++) {
                ULL ap = pack2(As[r * 130 + s]);
                ulonglong2 p = *(const ulonglong2*)(yp + s * 16);
                ulonglong2 q = *(const ulonglong2*)(yp + s * 16 + 4);
                ffma2(a0, ap, p.x); ffma2(a1, ap, p.y);
                ffma2(a2, ap, q.x); ffma2(a3, ap, q.y);
            }
            float2 f0 = u2f(a0), f1 = u2f(a1), f2 = u2f(a2), f3 = u2f(a3);
            float* zp = g_z + base + r * 16 + cg * 8;
            *(float4*)zp = make_float4(f0.x, f0.y, f1.x, f1.y);
            *(float4*)(zp + 4) = make_float4(f2.x, f2.y, f3.x, f3.y);
            float s1 = f0.x + f0.y + f1.x + f1.y + f2.x + f2.y + f3.x + f3.y;
            float s2 = f0.x * f0.x + f0.y * f0.y + f1.x * f1.x + f1.y * f1.y
                     + f2.x * f2.x + f2.y * f2.y + f3.x * f3.x + f3.y * f3.y;
            atomicAdd(&ssum[r], s1);
            atomicAdd(&ssq[r], s2);
        }
    } else if (FOUT == 4) {
        if (tid < 130) {
            int r = tid;
            ULL a0 = 0, a1 = 0;
            for (int s = 0; s < 130; s++) {
                ULL ap = pack2(As[r * 130 + s]);
                ulonglong2 p = *(const ulonglong2*)(ys + s * 4);
                ffma2(a0, ap, p.x); ffma2(a1, ap, p.y);
            }
            float2 f0 = u2f(a0), f1 = u2f(a1);
            *(float4*)(g_z + base + r * 16) = make_float4(f0.x, f0.y, f1.x, f1.y);
            ssum[r] = f0.x + f0.y + f1.x + f1.y;
            ssq[r] = f0.x * f0.x + f0.y * f0.y + f1.x * f1.x + f1.y * f1.y;
        }
    } else {  // FOUT == 2
        if (tid < 130) {
            int r = tid;
            ULL a0 = 0;
            for (int s = 0; s < 130; s++) {
                ULL ap = pack2(As[r * 130 + s]);
                ffma2(a0, ap, *(const ULL*)(ys + s * 2));
            }
            float2 f0 = u2f(a0);
            *(float2*)(g_z + base + r * 16) = f0;
            ssum[r] = f0.x + f0.y;
            ssq[r] = f0.x * f0.x + f0.y * f0.y;
        }
    }
    __syncthreads();
    if (tid < 130) {
        atomicAdd(&g_stats[SLOT][0][tid], ssum[tid]);
        atomicAdd(&g_stats[SLOT][1][tid], ssq[tid]);
    }
}

// h6 = relu(bn6(z6)) + h5; out = relu(flat(h6) @ w_mlp^T + b_mlp)
__global__ void __launch_bounds__(128) k_mlp(const float* __restrict__ wm,
        const float* __restrict__ bm, float* __restrict__ out,
        const float* __restrict__ gam, const float* __restrict__ bet) {
    __shared__ float red[2][4];
    const int b = blockIdx.x, tid = threadIdx.x;
    const float cinv = 1.f / 8192.f;
    float a0 = 0.f, a1 = 0.f;
    for (int i = tid; i < 260; i += 128) {
        int r = i >> 1, f = i & 1;
        float m = g_stats[6][0][r] * cinv;
        float v = g_stats[6][1][r] * cinv - m * m;
        float sc = gam[r] * rsqrtf(v + 1e-5f);
        float sh = bet[r] - sc * m;
        size_t gi = (size_t)b * 2080 + r * 16 + f;
        float hv = fmaxf(sc * g_z[gi] + sh, 0.f) + g_h[gi];
        a0 += hv * wm[i];
        a1 += hv * wm[260 + i];
    }
#pragma unroll
    for (int o = 16; o; o >>= 1) {
        a0 += __shfl_xor_sync(~0u, a0, o);
        a1 += __shfl_xor_sync(~0u, a1, o);
    }
    if ((tid & 31) == 0) { red[0][tid >> 5] = a0; red[1][tid >> 5] = a1; }
    __syncthreads();
    if (tid == 0) {
        float r0 = red[0][0] + red[0][1] + red[0][2] + red[0][3];
        float r1 = red[1][0] + red[1][1] + red[1][2] + red[1][3];
        out[b * 2 + 0] = fmaxf(r0 + bm[0], 0.f);
        out[b * 2 + 1] = fmaxf(r1 + bm[1], 0.f);
    }
}

extern "C" void kernel_launch(void* const* d_in, const int* in_sizes, int n_in,
                              void* d_out, int out_size) {
    (void)in_sizes; (void)n_in; (void)out_size;
    const float* X   = (const float*)d_in[0];
    const float* thr = (const float*)d_in[1];
    const float* wq  = (const float*)d_in[2];
    const float* bq  = (const float*)d_in[3];
    const float* g_t = (const float*)d_in[4];
    const float* b_t = (const float*)d_in[5];
    const float *w1 = (const float*)d_in[6],  *b1 = (const float*)d_in[7];
    const float *g1 = (const float*)d_in[8],  *e1 = (const float*)d_in[9];
    const float *w2 = (const float*)d_in[10], *b2 = (const float*)d_in[11];
    const float *g2 = (const float*)d_in[12], *e2 = (const float*)d_in[13];
    const float *w3 = (const float*)d_in[14], *b3 = (const float*)d_in[15];
    const float *g3 = (const float*)d_in[16], *e3 = (const float*)d_in[17];
    const float *w4 = (const float*)d_in[18], *b4 = (const float*)d_in[19];
    const float *g4 = (const float*)d_in[20], *e4 = (const float*)d_in[21];
    const float *w5 = (const float*)d_in[22], *b5 = (const float*)d_in[23];
    const float *g5 = (const float*)d_in[24], *e5 = (const float*)d_in[25];
    const float *w6 = (const float*)d_in[26], *b6 = (const float*)d_in[27];
    const float *g6 = (const float*)d_in[28], *e6 = (const float*)d_in[29];
    const float *wm = (const float*)d_in[30], *bm = (const float*)d_in[31];

    const int sm0  = (128 * 102 + 80 * 102) * 4;
    const int smA  = (16900 + 2080) * 4;
    const int smL2 = (16900 + 2080 + 2080) * 4;
    const int smL3 = (16900 + 2080 + 520) * 4;
    const int smL4 = (16900 + 520 + 520) * 4;
    const int smL5 = (16900 + 520 + 260) * 4;
    const int smL6 = (16900 + 260 + 260) * 4;
    cudaFuncSetAttribute(k_gemm0, cudaFuncAttributeMaxDynamicSharedMemorySize, sm0);
    cudaFuncSetAttribute(k_adjL1, cudaFuncAttributeMaxDynamicSharedMemorySize, smA);
    cudaFuncSetAttribute(k_layer<16,16,false,2>, cudaFuncAttributeMaxDynamicSharedMemorySize, smL2);
    cudaFuncSetAttribute(k_layer<16,4,true,3>,  cudaFuncAttributeMaxDynamicSharedMemorySize, smL3);
    cudaFuncSetAttribute(k_layer<4,4,false,4>,  cudaFuncAttributeMaxDynamicSharedMemorySize, smL4);
    cudaFuncSetAttribute(k_layer<4,2,true,5>,   cudaFuncAttributeMaxDynamicSharedMemorySize, smL5);
    cudaFuncSetAttribute(k_layer<2,2,false,6>,  cudaFuncAttributeMaxDynamicSharedMemorySize, smL6);

    k_zero<<<1, 256>>>();
    k_gemm0<<<4160, 256, sm0>>>(X, wq, bq, w1, b1);
    k_rel<<<4096, 352>>>();
    k_adjL1<<<4096, 256, smA>>>(thr, g_t, b_t);
    k_layer<16,16,false,2><<<4096, 256, smL2>>>(w2, b2, g1, e1, 1.f / 65536.f);
    k_layer<16,4,true,3><<<4096, 256, smL3>>>(w3, b3, g2, e2, 1.f / 65536.f);
    k_layer<4,4,false,4><<<4096, 256, smL4>>>(w4, b4, g3, e3, 1.f / 16384.f);
    k_layer<4,2,true,5><<<4096, 256, smL5>>>(w5, b5, g4, e4, 1.f / 16384.f);
    k_layer<2,2,false,6><<<4096, 256, smL6>>>(w6, b6, g5, e5, 1.f / 8192.f);
    k_mlp<<<4096, 128>>>(wm, bm, (float*)d_out, g6, e6);
}

// round 13
// speedup vs baseline: 1.8789x; 1.1846x over previous
#include <cuda_runtime.h>
#include <cuda_fp16.h>
#include <cstdint>
#include <math.h>

typedef unsigned long long ULL;

// B=4096 R=130 T=200 Q=64
__device__ float g_qky[(size_t)4096 * 130 * 80];    // qk(64) | y1(16), stride 80
__device__ float g_rel[(size_t)4096 * 130 * 130];   // raw rel (pre-BN), fp32
__device__ __half g_relh[(size_t)4096 * 130 * 130]; // A (post softmax/thr), fp16
__device__ float g_z[(size_t)4096 * 130 * 16];      // pre-BN z (stride 16)
__device__ float g_h[(size_t)4096 * 130 * 16];      // h_i (stride 16)
__device__ float g_stats[7][2][130];                // (sum, sumsq) per channel

__device__ __forceinline__ void ffma2(ULL& d, ULL a, ULL b) {
    asm("fma.rn.f32x2 %0, %1, %2, %0;" : "+l"(d) : "l"(a), "l"(b));
}
__device__ __forceinline__ ULL pack2(float v) {
    ULL r; asm("mov.b64 %0, {%1, %1};" : "=l"(r) : "f"(v)); return r;
}
__device__ __forceinline__ float2 u2f(ULL u) {
    float2 f; asm("mov.b64 {%0, %1}, %2;" : "=f"(f.x), "=f"(f.y) : "l"(u)); return f;
}
__device__ __forceinline__ void cpa8(void* dst, const void* src) {
    unsigned d = (unsigned)__cvta_generic_to_shared(dst);
    asm volatile("cp.async.ca.shared.global [%0], [%1], 8;" :: "r"(d), "l"(src));
}
__device__ __forceinline__ void cpwait() {
    asm volatile("cp.async.wait_all;" ::: "memory");
}

__global__ void k_zero() {
    float* p = &g_stats[0][0][0];
    for (int i = threadIdx.x; i < 7 * 2 * 130; i += 256) p[i] = 0.f;
}

// C[m,n] = sum_t clean(X)[m,t] * W[n,t] + bias   (W=[wq;w1], M=B*R, N=80, K=200)
__global__ void __launch_bounds__(256) k_gemm0(const float* __restrict__ X,
        const float* __restrict__ wq, const float* __restrict__ bq,
        const float* __restrict__ w1, const float* __restrict__ b1) {
    extern __shared__ float sm[];
    float* Xs = sm;                // 128 x 102
    float* Ws = sm + 128 * 102;    // 80 x 102
    const int tid = threadIdx.x;
    const int tx = tid & 15, ty = tid >> 4;
    const size_t m0 = (size_t)blockIdx.x * 128;
    ULL acc[8][5];
#pragma unroll
    for (int i = 0; i < 8; i++)
#pragma unroll
        for (int j = 0; j < 5; j++) acc[i][j] = 0ull;

    for (int kc = 0; kc < 2; kc++) {
        for (int i = tid; i < 128 * 50; i += 256) {
            int r = i / 50, c = (i % 50) * 2;
            float2 v = *(const float2*)(X + (m0 + r) * 200 + kc * 100 + c);
            if (!(v.x == v.x)) v.x = 0.f;
            if (!(v.y == v.y)) v.y = 0.f;
            *(float2*)(Xs + r * 102 + c) = v;
        }
        for (int i = tid; i < 80 * 50; i += 256) {
            int r = i / 50, c = (i % 50) * 2;
            const float* src = (r < 64) ? wq + r * 200 : w1 + (r - 64) * 200;
            *(float2*)(Ws + r * 102 + c) = *(const float2*)(src + kc * 100 + c);
        }
        __syncthreads();
#pragma unroll 5
        for (int kk = 0; kk < 50; kk++) {
            ULL xv[8], wv[5];
#pragma unroll
            for (int i = 0; i < 8; i++)
                xv[i] = *(const ULL*)(Xs + (ty * 8 + i) * 102 + 2 * kk);
#pragma unroll
            for (int j = 0; j < 5; j++)
                wv[j] = *(const ULL*)(Ws + (tx * 5 + j) * 102 + 2 * kk);
#pragma unroll
            for (int i = 0; i < 8; i++)
#pragma unroll
                for (int j = 0; j < 5; j++) ffma2(acc[i][j], xv[i], wv[j]);
        }
        __syncthreads();
    }
#pragma unroll
    for (int j = 0; j < 5; j++) {
        int n = tx * 5 + j;
        float bias = (n < 64) ? bq[n] : b1[n - 64];
#pragma unroll
        for (int i = 0; i < 8; i++) {
            float2 f = u2f(acc[i][j]);
            g_qky[(m0 + ty * 8 + i) * 80 + n] = f.x + f.y + bias;
        }
    }
}

// rel[b,r,s] = sum_q qk[b,r,q] * flat[b, q*130+s]; 5x10 f32x2 tiles; BN0 stats
__global__ void __launch_bounds__(352) k_rel() {
    __shared__ float ba[130 * 64];     // qk row-major
    __shared__ float bk[64 * 132];     // flat reshaped, padded
    __shared__ float ssum[130], ssq[130];
    const int b = blockIdx.x, tid = threadIdx.x;
    const float* qk = g_qky + (size_t)b * 10400;
    for (int f = tid; f < 8320; f += 352) {
        float v = qk[(f >> 6) * 80 + (f & 63)];
        ba[f] = v;
        bk[(f / 130) * 132 + (f % 130)] = v;
    }
    if (tid < 130) { ssum[tid] = 0.f; ssq[tid] = 0.f; }
    __syncthreads();
    float* out = g_rel + (size_t)b * 16900;
    if (tid < 338) {
        const int tr = tid / 13, ts = tid - tr * 13;
        const int r0 = tr * 5, s0 = ts * 10;
        ULL acc[5][5];
#pragma unroll
        for (int i = 0; i < 5; i++)
#pragma unroll
            for (int j = 0; j < 5; j++) acc[i][j] = 0ull;
        for (int q = 0; q < 64; q++) {
            ULL kv[5];
#pragma unroll
            for (int j = 0; j < 5; j++) kv[j] = *(const ULL*)(bk + q * 132 + s0 + 2 * j);
#pragma unroll
            for (int i = 0; i < 5; i++) {
                ULL ap = pack2(ba[(r0 + i) * 64 + q]);
#pragma unroll
                for (int j = 0; j < 5; j++) ffma2(acc[i][j], ap, kv[j]);
            }
        }
#pragma unroll
        for (int i = 0; i < 5; i++) {
            float s = 0.f, s2 = 0.f;
#pragma unroll
            for (int j = 0; j < 5; j++) {
                float2 f = u2f(acc[i][j]);
                *(float2*)(out + (r0 + i) * 130 + s0 + 2 * j) = f;
                s += f.x + f.y; s2 += f.x * f.x + f.y * f.y;
            }
            atomicAdd(&ssum[r0 + i], s);
            atomicAdd(&ssq[r0 + i], s2);
        }
    }
    __syncthreads();
    if (tid < 130) {
        atomicAdd(&g_stats[0][0][tid], ssum[tid]);
        atomicAdd(&g_stats[0][1][tid], ssq[tid]);
    }
}

// BN0 + softmax + relu(-thr) -> A (fp16 gmem + smem), z1 = A @ y1, BN1 stats
__global__ void __launch_bounds__(256) k_adjL1(const float* __restrict__ thr_p,
        const float* __restrict__ gam, const float* __restrict__ bet) {
    extern __shared__ float sm[];
    float* ys = sm;                         // 130*16 floats (ofs 0, 16B aligned)
    __half* Ah = (__half*)(sm + 2080);      // 132*130 halves (ofs 8320, 8B aligned)
    __shared__ float2 sss[130];
    __shared__ float ssum[130], ssq[130];
    const int b = blockIdx.x, tid = threadIdx.x;
    const float thr = *thr_p;
    const float* rel = g_rel + (size_t)b * 16900;
    __half* relh = g_relh + (size_t)b * 16900;
    if (tid < 130) {
        const float cinv = 1.f / 532480.f;
        float m = g_stats[0][0][tid] * cinv;
        float v = g_stats[0][1][tid] * cinv - m * m;
        float sc = gam[tid] * rsqrtf(v + 1e-5f);
        sss[tid] = make_float2(sc, bet[tid] - sc * m);
        ssum[tid] = 0.f; ssq[tid] = 0.f;
        ((uint32_t*)Ah)[8450 + tid] = 0u;   // zero pad rows 130,131
    }
    for (int i = tid; i < 2080; i += 256)
        ys[i] = g_qky[(size_t)b * 10400 + (i >> 4) * 80 + 64 + (i & 15)];
    __syncthreads();
    const int w = tid >> 5, lane = tid & 31;
    for (int r = w; r < 130; r += 8) {
        float2 ss = sss[r];
        float v[5];
        float mx = -1e30f;
#pragma unroll
        for (int k = 0; k < 5; k++) {
            int s = lane + 32 * k;
            v[k] = (s < 130) ? (ss.x * rel[r * 130 + s] + ss.y) : -1e30f;
            mx = fmaxf(mx, v[k]);
        }
#pragma unroll
        for (int o = 16; o; o >>= 1) mx = fmaxf(mx, __shfl_xor_sync(~0u, mx, o));
        float e[5], sum = 0.f;
#pragma unroll
        for (int k = 0; k < 5; k++) {
            int s = lane + 32 * k;
            e[k] = (s < 130) ? __expf(v[k] - mx) : 0.f;
            sum += e[k];
        }
#pragma unroll
        for (int o = 16; o; o >>= 1) sum += __shfl_xor_sync(~0u, sum, o);
        float inv = 1.f / sum;
#pragma unroll
        for (int k = 0; k < 5; k++) {
            int s = lane + 32 * k;
            if (s < 130) {
                __half a = __float2half(fmaxf(e[k] * inv - thr, 0.f));
                Ah[r * 130 + s] = a;
                relh[r * 130 + s] = a;
            }
        }
    }
    __syncthreads();
    if (tid < 66) {
        const int r0 = (tid >> 1) * 4, cg = tid & 1;
        const float* yb = ys + cg * 8;
        ULL acc[4][4];
#pragma unroll
        for (int i = 0; i < 4; i++)
#pragma unroll
            for (int j = 0; j < 4; j++) acc[i][j] = 0ull;
        for (int sp = 0; sp < 65; sp++) {
            float2 af[4];
#pragma unroll
            for (int i = 0; i < 4; i++)
                af[i] = __half22float2(*(const __half2*)(Ah + (r0 + i) * 130 + 2 * sp));
            ulonglong2 p0 = *(const ulonglong2*)(yb + (2 * sp) * 16);
            ulonglong2 p1 = *(const ulonglong2*)(yb + (2 * sp) * 16 + 4);
            ulonglong2 q0 = *(const ulonglong2*)(yb + (2 * sp + 1) * 16);
            ulonglong2 q1 = *(const ulonglong2*)(yb + (2 * sp + 1) * 16 + 4);
#pragma unroll
            for (int i = 0; i < 4; i++) {
                ULL a0 = pack2(af[i].x), a1 = pack2(af[i].y);
                ffma2(acc[i][0], a0, p0.x); ffma2(acc[i][1], a0, p0.y);
                ffma2(acc[i][2], a0, p1.x); ffma2(acc[i][3], a0, p1.y);
                ffma2(acc[i][0], a1, q0.x); ffma2(acc[i][1], a1, q0.y);
                ffma2(acc[i][2], a1, q1.x); ffma2(acc[i][3], a1, q1.y);
            }
        }
#pragma unroll
        for (int i = 0; i < 4; i++) {
            int r = r0 + i;
            if (r < 130) {
                float2 f0 = u2f(acc[i][0]), f1 = u2f(acc[i][1]);
                float2 f2 = u2f(acc[i][2]), f3 = u2f(acc[i][3]);
                float* zp = g_z + (size_t)b * 2080 + r * 16 + cg * 8;
                *(float4*)zp = make_float4(f0.x, f0.y, f1.x, f1.y);
                *(float4*)(zp + 4) = make_float4(f2.x, f2.y, f3.x, f3.y);
                float s1 = f0.x + f0.y + f1.x + f1.y + f2.x + f2.y + f3.x + f3.y;
                float s2 = f0.x * f0.x + f0.y * f0.y + f1.x * f1.x + f1.y * f1.y
                         + f2.x * f2.x + f2.y * f2.y + f3.x * f3.x + f3.y * f3.y;
                atomicAdd(&ssum[r], s1);
                atomicAdd(&ssq[r], s2);
            }
        }
    }
    __syncthreads();
    if (tid < 130) {
        atomicAdd(&g_stats[1][0][tid], ssum[tid]);
        atomicAdd(&g_stats[1][1][tid], ssq[tid]);
    }
}

// h = relu(bn_{SLOT-1}(z)) [+res]; g_h = h; y = h@w^T+b; z = A@y; stats[SLOT]
template <int FIN, int FOUT, bool RES, int SLOT>
__global__ void __launch_bounds__(256) k_layer(const float* __restrict__ w,
        const float* __restrict__ bias, const float* __restrict__ gam,
        const float* __restrict__ bet, float cinv) {
    extern __shared__ float sm[];
    float* hs = sm;                                  // 130*FIN
    float* ys = sm + 130 * FIN;                      // 130*FOUT
    __half* Ah = (__half*)(sm + 130 * FIN + 130 * FOUT); // 132*130 halves
    __shared__ float ws[FOUT * FIN], bs_[FOUT];
    __shared__ float2 sss[130];
    __shared__ float ssum[130], ssq[130];
    const int b = blockIdx.x, tid = threadIdx.x;
    const __half* relh = g_relh + (size_t)b * 16900;
    for (int i = tid; i < 4225; i += 256)
        cpa8(Ah + i * 4, relh + i * 4);
    if (tid < FOUT * FIN) ws[tid] = w[tid];
    if (tid < FOUT) bs_[tid] = bias[tid];
    if (tid < 130) {
        float m = g_stats[SLOT - 1][0][tid] * cinv;
        float v = g_stats[SLOT - 1][1][tid] * cinv - m * m;
        float sc = gam[tid] * rsqrtf(v + 1e-5f);
        sss[tid] = make_float2(sc, bet[tid] - sc * m);
        ssum[tid] = 0.f; ssq[tid] = 0.f;
        ((uint32_t*)Ah)[8450 + tid] = 0u;            // zero pad rows
    }
    __syncthreads();
    const size_t base = (size_t)b * 2080;
    if (FIN == 16) {
        for (int i4 = tid; i4 < 520; i4 += 256) {
            int r = i4 >> 2;
            float2 ss = sss[r];
            float4 z = *(const float4*)(g_z + base + 4 * i4);
            float4 h4;
            h4.x = fmaxf(ss.x * z.x + ss.y, 0.f);
            h4.y = fmaxf(ss.x * z.y + ss.y, 0.f);
            h4.z = fmaxf(ss.x * z.z + ss.y, 0.f);
            h4.w = fmaxf(ss.x * z.w + ss.y, 0.f);
            if (RES) {
                float4 p = *(const float4*)(g_h + base + 4 * i4);
                h4.x += p.x; h4.y += p.y; h4.z += p.z; h4.w += p.w;
            }
            *(float4*)(hs + 4 * i4) = h4;
            *(float4*)(g_h + base + 4 * i4) = h4;
        }
    } else if (FIN == 4) {
        if (tid < 130) {
            float2 ss = sss[tid];
            float4 z = *(const float4*)(g_z + base + tid * 16);
            float4 h4;
            h4.x = fmaxf(ss.x * z.x + ss.y, 0.f);
            h4.y = fmaxf(ss.x * z.y + ss.y, 0.f);
            h4.z = fmaxf(ss.x * z.z + ss.y, 0.f);
            h4.w = fmaxf(ss.x * z.w + ss.y, 0.f);
            if (RES) {
                float4 p = *(const float4*)(g_h + base + tid * 16);
                h4.x += p.x; h4.y += p.y; h4.z += p.z; h4.w += p.w;
            }
            *(float4*)(hs + tid * 4) = h4;
            *(float4*)(g_h + base + tid * 16) = h4;
        }
    } else {  // FIN == 2
        if (tid < 130) {
            float2 ss = sss[tid];
            float2 z = *(const float2*)(g_z + base + tid * 16);
            float2 h2;
            h2.x = fmaxf(ss.x * z.x + ss.y, 0.f);
            h2.y = fmaxf(ss.x * z.y + ss.y, 0.f);
            if (RES) {
                float2 p = *(const float2*)(g_h + base + tid * 16);
                h2.x += p.x; h2.y += p.y;
            }
            *(float2*)(hs + tid * 2) = h2;
            *(float2*)(g_h + base + tid * 16) = h2;
        }
    }
    __syncthreads();
    for (int o = tid; o < 130 * FOUT; o += 256) {
        int r = o / FOUT, fo = o % FOUT;
        float acc = bs_[fo];
#pragma unroll
        for (int f = 0; f < FIN; f++) acc += hs[r * FIN + f] * ws[fo * FIN + f];
        ys[o] = acc;
    }
    cpwait();
    __syncthreads();
    if (FOUT == 16) {
        if (tid < 66) {
            const int r0 = (tid >> 1) * 4, cg = tid & 1;
            const float* yb = ys + cg * 8;
            ULL acc[4][4];
#pragma unroll
            for (int i = 0; i < 4; i++)
#pragma unroll
                for (int j = 0; j < 4; j++) acc[i][j] = 0ull;
            for (int sp = 0; sp < 65; sp++) {
                float2 af[4];
#pragma unroll
                for (int i = 0; i < 4; i++)
                    af[i] = __half22float2(*(const __half2*)(Ah + (r0 + i) * 130 + 2 * sp));
                ulonglong2 p0 = *(const ulonglong2*)(yb + (2 * sp) * 16);
                ulonglong2 p1 = *(const ulonglong2*)(yb + (2 * sp) * 16 + 4);
                ulonglong2 q0 = *(const ulonglong2*)(yb + (2 * sp + 1) * 16);
                ulonglong2 q1 = *(const ulonglong2*)(yb + (2 * sp + 1) * 16 + 4);
#pragma unroll
                for (int i = 0; i < 4; i++) {
                    ULL a0 = pack2(af[i].x), a1 = pack2(af[i].y);
                    ffma2(acc[i][0], a0, p0.x); ffma2(acc[i][1], a0, p0.y);
                    ffma2(acc[i][2], a0, p1.x); ffma2(acc[i][3], a0, p1.y);
                    ffma2(acc[i][0], a1, q0.x); ffma2(acc[i][1], a1, q0.y);
                    ffma2(acc[i][2], a1, q1.x); ffma2(acc[i][3], a1, q1.y);
                }
            }
#pragma unroll
            for (int i = 0; i < 4; i++) {
                int r = r0 + i;
                if (r < 130) {
                    float2 f0 = u2f(acc[i][0]), f1 = u2f(acc[i][1]);
                    float2 f2 = u2f(acc[i][2]), f3 = u2f(acc[i][3]);
                    float* zp = g_z + base + r * 16 + cg * 8;
                    *(float4*)zp = make_float4(f0.x, f0.y, f1.x, f1.y);
                    *(float4*)(zp + 4) = make_float4(f2.x, f2.y, f3.x, f3.y);
                    float s1 = f0.x + f0.y + f1.x + f1.y + f2.x + f2.y + f3.x + f3.y;
                    float s2 = f0.x * f0.x + f0.y * f0.y + f1.x * f1.x + f1.y * f1.y
                             + f2.x * f2.x + f2.y * f2.y + f3.x * f3.x + f3.y * f3.y;
                    atomicAdd(&ssum[r], s1);
                    atomicAdd(&ssq[r], s2);
                }
            }
        }
    } else if (FOUT == 4) {
        if (tid < 33) {
            const int r0 = tid * 4;
            ULL acc[4][2];
#pragma unroll
            for (int i = 0; i < 4; i++) { acc[i][0] = 0ull; acc[i][1] = 0ull; }
            for (int sp = 0; sp < 65; sp++) {
                float2 af[4];
#pragma unroll
                for (int i = 0; i < 4; i++)
                    af[i] = __half22float2(*(const __half2*)(Ah + (r0 + i) * 130 + 2 * sp));
                ulonglong2 y0 = *(const ulonglong2*)(ys + (2 * sp) * 4);
                ulonglong2 y1 = *(const ulonglong2*)(ys + (2 * sp + 1) * 4);
#pragma unroll
                for (int i = 0; i < 4; i++) {
                    ULL a0 = pack2(af[i].x), a1 = pack2(af[i].y);
                    ffma2(acc[i][0], a0, y0.x); ffma2(acc[i][1], a0, y0.y);
                    ffma2(acc[i][0], a1, y1.x); ffma2(acc[i][1], a1, y1.y);
                }
            }
#pragma unroll
            for (int i = 0; i < 4; i++) {
                int r = r0 + i;
                if (r < 130) {
                    float2 f0 = u2f(acc[i][0]), f1 = u2f(acc[i][1]);
                    *(float4*)(g_z + base + r * 16) = make_float4(f0.x, f0.y, f1.x, f1.y);
                    ssum[r] = f0.x + f0.y + f1.x + f1.y;
                    ssq[r] = f0.x * f0.x + f0.y * f0.y + f1.x * f1.x + f1.y * f1.y;
                }
            }
        }
    } else {  // FOUT == 2
        if (tid < 33) {
            const int r0 = tid * 4;
            ULL acc[4];
#pragma unroll
            for (int i = 0; i < 4; i++) acc[i] = 0ull;
            for (int sp = 0; sp < 65; sp++) {
                float2 af[4];
#pragma unroll
                for (int i = 0; i < 4; i++)
                    af[i] = __half22float2(*(const __half2*)(Ah + (r0 + i) * 130 + 2 * sp));
                ULL y0 = *(const ULL*)(ys + (2 * sp) * 2);
                ULL y1 = *(const ULL*)(ys + (2 * sp + 1) * 2);
#pragma unroll
                for (int i = 0; i < 4; i++) {
                    ffma2(acc[i], pack2(af[i].x), y0);
                    ffma2(acc[i], pack2(af[i].y), y1);
                }
            }
#pragma unroll
            for (int i = 0; i < 4; i++) {
                int r = r0 + i;
                if (r < 130) {
                    float2 f0 = u2f(acc[i]);
                    *(float2*)(g_z + base + r * 16) = f0;
                    ssum[r] = f0.x + f0.y;
                    ssq[r] = f0.x * f0.x + f0.y * f0.y;
                }
            }
        }
    }
    __syncthreads();
    if (tid < 130) {
        atomicAdd(&g_stats[SLOT][0][tid], ssum[tid]);
        atomicAdd(&g_stats[SLOT][1][tid], ssq[tid]);
    }
}

// h6 = relu(bn6(z6)) + h5; out = relu(flat(h6) @ w_mlp^T + b_mlp)
__global__ void __launch_bounds__(128) k_mlp(const float* __restrict__ wm,
        const float* __restrict__ bm, float* __restrict__ out,
        const float* __restrict__ gam, const float* __restrict__ bet) {
    __shared__ float red[2][4];
    const int b = blockIdx.x, tid = threadIdx.x;
    const float cinv = 1.f / 8192.f;
    float a0 = 0.f, a1 = 0.f;
    for (int i = tid; i < 260; i += 128) {
        int r = i >> 1, f = i & 1;
        float m = g_stats[6][0][r] * cinv;
        float v = g_stats[6][1][r] * cinv - m * m;
        float sc = gam[r] * rsqrtf(v + 1e-5f);
        float sh = bet[r] - sc * m;
        size_t gi = (size_t)b * 2080 + r * 16 + f;
        float hv = fmaxf(sc * g_z[gi] + sh, 0.f) + g_h[gi];
        a0 += hv * wm[i];
        a1 += hv * wm[260 + i];
    }
#pragma unroll
    for (int o = 16; o; o >>= 1) {
        a0 += __shfl_xor_sync(~0u, a0, o);
        a1 += __shfl_xor_sync(~0u, a1, o);
    }
    if ((tid & 31) == 0) { red[0][tid >> 5] = a0; red[1][tid >> 5] = a1; }
    __syncthreads();
    if (tid == 0) {
        float r0 = red[0][0] + red[0][1] + red[0][2] + red[0][3];
        float r1 = red[1][0] + red[1][1] + red[1][2] + red[1][3];
        out[b * 2 + 0] = fmaxf(r0 + bm[0], 0.f);
        out[b * 2 + 1] = fmaxf(r1 + bm[1], 0.f);
    }
}

extern "C" void kernel_launch(void* const* d_in, const int* in_sizes, int n_in,
                              void* d_out, int out_size) {
    (void)in_sizes; (void)n_in; (void)out_size;
    const float* X   = (const float*)d_in[0];
    const float* thr = (const float*)d_in[1];
    const float* wq  = (const float*)d_in[2];
    const float* bq  = (const float*)d_in[3];
    const float* g_t = (const float*)d_in[4];
    const float* b_t = (const float*)d_in[5];
    const float *w1 = (const float*)d_in[6],  *b1 = (const float*)d_in[7];
    const float *g1 = (const float*)d_in[8],  *e1 = (const float*)d_in[9];
    const float *w2 = (const float*)d_in[10], *b2 = (const float*)d_in[11];
    const float *g2 = (const float*)d_in[12], *e2 = (const float*)d_in[13];
    const float *w3 = (const float*)d_in[14], *b3 = (const float*)d_in[15];
    const float *g3 = (const float*)d_in[16], *e3 = (const float*)d_in[17];
    const float *w4 = (const float*)d_in[18], *b4 = (const float*)d_in[19];
    const float *g4 = (const float*)d_in[20], *e4 = (const float*)d_in[21];
    const float *w5 = (const float*)d_in[22], *b5 = (const float*)d_in[23];
    const float *g5 = (const float*)d_in[24], *e5 = (const float*)d_in[25];
    const float *w6 = (const float*)d_in[26], *b6 = (const float*)d_in[27];
    const float *g6 = (const float*)d_in[28], *e6 = (const float*)d_in[29];
    const float *wm = (const float*)d_in[30], *bm = (const float*)d_in[31];

    const int sm0  = (128 * 102 + 80 * 102) * 4;
    const int smA  = 2080 * 4 + 17160 * 2;                  // ys + Ah(pad)
    const int smL2 = (2080 + 2080) * 4 + 17160 * 2;
    const int smL3 = (2080 + 520) * 4 + 17160 * 2;
    const int smL4 = (520 + 520) * 4 + 17160 * 2;
    const int smL5 = (520 + 260) * 4 + 17160 * 2;
    const int smL6 = (260 + 260) * 4 + 17160 * 2;
    cudaFuncSetAttribute(k_gemm0, cudaFuncAttributeMaxDynamicSharedMemorySize, sm0);
    cudaFuncSetAttribute(k_adjL1, cudaFuncAttributeMaxDynamicSharedMemorySize, smA);
    cudaFuncSetAttribute(k_layer<16,16,false,2>, cudaFuncAttributeMaxDynamicSharedMemorySize, smL2);
    cudaFuncSetAttribute(k_layer<16,4,true,3>,  cudaFuncAttributeMaxDynamicSharedMemorySize, smL3);
    cudaFuncSetAttribute(k_layer<4,4,false,4>,  cudaFuncAttributeMaxDynamicSharedMemorySize, smL4);
    cudaFuncSetAttribute(k_layer<4,2,true,5>,   cudaFuncAttributeMaxDynamicSharedMemorySize, smL5);
    cudaFuncSetAttribute(k_layer<2,2,false,6>,  cudaFuncAttributeMaxDynamicSharedMemorySize, smL6);

    k_zero<<<1, 256>>>();
    k_gemm0<<<4160, 256, sm0>>>(X, wq, bq, w1, b1);
    k_rel<<<4096, 352>>>();
    k_adjL1<<<4096, 256, smA>>>(thr, g_t, b_t);
    k_layer<16,16,false,2><<<4096, 256, smL2>>>(w2, b2, g1, e1, 1.f / 65536.f);
    k_layer<16,4,true,3><<<4096, 256, smL3>>>(w3, b3, g2, e2, 1.f / 65536.f);
    k_layer<4,4,false,4><<<4096, 256, smL4>>>(w4, b4, g3, e3, 1.f / 16384.f);
    k_layer<4,2,true,5><<<4096, 256, smL5>>>(w5, b5, g4, e4, 1.f / 16384.f);
    k_layer<2,2,false,6><<<4096, 256, smL6>>>(w6, b6, g5, e5, 1.f / 8192.f);
    k_mlp<<<4096, 128>>>(wm, bm, (float*)d_out, g6, e6);
}

// round 14
// speedup vs baseline: 1.9110x; 1.0171x over previous
#include <cuda_runtime.h>
#include <cuda_fp16.h>
#include <cstdint>
#include <math.h>

typedef unsigned long long ULL;

// B=4096 R=130 T=200 Q=64
__device__ float g_qky[(size_t)4096 * 130 * 80];    // qk(64) | y1(16), stride 80
__device__ __half g_relh[(size_t)4096 * 130 * 130]; // A (post softmax/thr), fp16
__device__ float g_z[(size_t)4096 * 130 * 16];      // pre-BN z (stride 16)
__device__ float g_h[(size_t)4096 * 130 * 16];      // h_i (stride 16)
__device__ float g_stats[7][2][130];                // (sum, sumsq) per channel

__device__ __forceinline__ void ffma2(ULL& d, ULL a, ULL b) {
    asm("fma.rn.f32x2 %0, %1, %2, %0;" : "+l"(d) : "l"(a), "l"(b));
}
__device__ __forceinline__ ULL pack2(float v) {
    ULL r; asm("mov.b64 %0, {%1, %1};" : "=l"(r) : "f"(v)); return r;
}
__device__ __forceinline__ ULL packf2(float x, float y) {
    ULL r; asm("mov.b64 %0, {%1, %2};" : "=l"(r) : "f"(x), "f"(y)); return r;
}
__device__ __forceinline__ float2 u2f(ULL u) {
    float2 f; asm("mov.b64 {%0, %1}, %2;" : "=f"(f.x), "=f"(f.y) : "l"(u)); return f;
}
__device__ __forceinline__ void cpa8(void* dst, const void* src) {
    unsigned d = (unsigned)__cvta_generic_to_shared(dst);
    asm volatile("cp.async.ca.shared.global [%0], [%1], 8;" :: "r"(d), "l"(src));
}
__device__ __forceinline__ void cpwait() {
    asm volatile("cp.async.wait_all;" ::: "memory");
}

__global__ void k_zero() {
    float* p = &g_stats[0][0][0];
    for (int i = threadIdx.x; i < 7 * 2 * 130; i += 256) p[i] = 0.f;
}

// C[m,n] = sum_t clean(X)[m,t] * W[n,t] + bias   (W=[wq;w1], M=B*R, N=80, K=200)
__global__ void __launch_bounds__(256) k_gemm0(const float* __restrict__ X,
        const float* __restrict__ wq, const float* __restrict__ bq,
        const float* __restrict__ w1, const float* __restrict__ b1) {
    extern __shared__ float sm[];
    float* Xs = sm;                // 128 x 102
    float* Ws = sm + 128 * 102;    // 80 x 102
    const int tid = threadIdx.x;
    const int tx = tid & 15, ty = tid >> 4;
    const size_t m0 = (size_t)blockIdx.x * 128;
    ULL acc[8][5];
#pragma unroll
    for (int i = 0; i < 8; i++)
#pragma unroll
        for (int j = 0; j < 5; j++) acc[i][j] = 0ull;

    for (int kc = 0; kc < 2; kc++) {
        for (int i = tid; i < 128 * 50; i += 256) {
            int r = i / 50, c = (i % 50) * 2;
            float2 v = *(const float2*)(X + (m0 + r) * 200 + kc * 100 + c);
            if (!(v.x == v.x)) v.x = 0.f;
            if (!(v.y == v.y)) v.y = 0.f;
            *(float2*)(Xs + r * 102 + c) = v;
        }
        for (int i = tid; i < 80 * 50; i += 256) {
            int r = i / 50, c = (i % 50) * 2;
            const float* src = (r < 64) ? wq + r * 200 : w1 + (r - 64) * 200;
            *(float2*)(Ws + r * 102 + c) = *(const float2*)(src + kc * 100 + c);
        }
        __syncthreads();
#pragma unroll 5
        for (int kk = 0; kk < 50; kk++) {
            ULL xv[8], wv[5];
#pragma unroll
            for (int i = 0; i < 8; i++)
                xv[i] = *(const ULL*)(Xs + (ty * 8 + i) * 102 + 2 * kk);
#pragma unroll
            for (int j = 0; j < 5; j++)
                wv[j] = *(const ULL*)(Ws + (tx * 5 + j) * 102 + 2 * kk);
#pragma unroll
            for (int i = 0; i < 8; i++)
#pragma unroll
                for (int j = 0; j < 5; j++) ffma2(acc[i][j], xv[i], wv[j]);
        }
        __syncthreads();
    }
#pragma unroll
    for (int j = 0; j < 5; j++) {
        int n = tx * 5 + j;
        float bias = (n < 64) ? bq[n] : b1[n - 64];
#pragma unroll
        for (int i = 0; i < 8; i++) {
            float2 f = u2f(acc[i][j]);
            g_qky[(m0 + ty * 8 + i) * 80 + n] = f.x + f.y + bias;
        }
    }
}

// BN0 stats only: rel[b,r,s] GEMM in regs, accumulate per-row sum/sumsq. No rel write.
__global__ void __launch_bounds__(352) k_rel() {
    __shared__ float ba[130 * 64];     // qk row-major
    __shared__ float bk[64 * 132];     // flat reshaped, padded
    __shared__ float ssum[130], ssq[130];
    const int b = blockIdx.x, tid = threadIdx.x;
    const float* qk = g_qky + (size_t)b * 10400;
    for (int f = tid; f < 8320; f += 352) {
        float v = qk[(f >> 6) * 80 + (f & 63)];
        ba[f] = v;
        bk[(f / 130) * 132 + (f % 130)] = v;
    }
    if (tid < 130) { ssum[tid] = 0.f; ssq[tid] = 0.f; }
    __syncthreads();
    if (tid < 338) {
        const int tr = tid / 13, ts = tid - tr * 13;
        const int r0 = tr * 5, s0 = ts * 10;
        ULL acc[5][5];
#pragma unroll
        for (int i = 0; i < 5; i++)
#pragma unroll
            for (int j = 0; j < 5; j++) acc[i][j] = 0ull;
        for (int q = 0; q < 64; q++) {
            ULL kv[5];
#pragma unroll
            for (int j = 0; j < 5; j++) kv[j] = *(const ULL*)(bk + q * 132 + s0 + 2 * j);
#pragma unroll
            for (int i = 0; i < 5; i++) {
                ULL ap = pack2(ba[(r0 + i) * 64 + q]);
#pragma unroll
                for (int j = 0; j < 5; j++) ffma2(acc[i][j], ap, kv[j]);
            }
        }
#pragma unroll
        for (int i = 0; i < 5; i++) {
            float s = 0.f, s2 = 0.f;
#pragma unroll
            for (int j = 0; j < 5; j++) {
                float2 f = u2f(acc[i][j]);
                s += f.x + f.y; s2 += f.x * f.x + f.y * f.y;
            }
            atomicAdd(&ssum[r0 + i], s);
            atomicAdd(&ssq[r0 + i], s2);
        }
    }
    __syncthreads();
    if (tid < 130) {
        atomicAdd(&g_stats[0][0][tid], ssum[tid]);
        atomicAdd(&g_stats[0][1][tid], ssq[tid]);
    }
}

// Recompute rel GEMM in regs; softmax(sc*rel) (shift cancels, no max needed);
// relu(-thr) -> A fp16 (smem + gmem); z1 = A @ y1; BN1 stats.
__global__ void __launch_bounds__(352, 2) k_adjL1(const float* __restrict__ thr_p,
        const float* __restrict__ gam) {
    extern __shared__ float sm[];
    float* ba = sm;                    // phase1: 8320 floats
    float* bk = sm + 8580;             // phase1: 8448 floats
    __half* Ah = (__half*)sm;          // phase2: 16900 halves (region1 = 8580 floats)
    float* ys = sm + 8580;             // phase2: 2080 floats (region2)
    __shared__ float rsum[130], ssc[130], ssum[130], ssq[130];
    const int b = blockIdx.x, tid = threadIdx.x;
    const float thr = *thr_p;
    const float* qk = g_qky + (size_t)b * 10400;
    for (int f = tid; f < 8320; f += 352) {
        float v = qk[(f >> 6) * 80 + (f & 63)];
        ba[f] = v;
        bk[(f / 130) * 132 + (f % 130)] = v;
    }
    if (tid < 130) {
        const float cinv = 1.f / 532480.f;
        float m = g_stats[0][0][tid] * cinv;
        float va = g_stats[0][1][tid] * cinv - m * m;
        ssc[tid] = gam[tid] * rsqrtf(va + 1e-5f);
        rsum[tid] = 0.f; ssum[tid] = 0.f; ssq[tid] = 0.f;
    }
    __syncthreads();
    const int tr = tid / 13, ts = tid - tr * 13;
    const int r0 = tr * 5, s0 = ts * 10;
    ULL acc[5][5];
#pragma unroll
    for (int i = 0; i < 5; i++)
#pragma unroll
        for (int j = 0; j < 5; j++) acc[i][j] = 0ull;
    if (tid < 338) {
        for (int q = 0; q < 64; q++) {
            ULL kv[5];
#pragma unroll
            for (int j = 0; j < 5; j++) kv[j] = *(const ULL*)(bk + q * 132 + s0 + 2 * j);
#pragma unroll
            for (int i = 0; i < 5; i++) {
                ULL ap = pack2(ba[(r0 + i) * 64 + q]);
#pragma unroll
                for (int j = 0; j < 5; j++) ffma2(acc[i][j], ap, kv[j]);
            }
        }
    }
    __syncthreads();   // ba/bk dead; regions become Ah/ys
    for (int i = tid; i < 2080; i += 352)
        ys[i] = qk[(i >> 4) * 80 + 64 + (i & 15)];
    if (tid < 338) {
#pragma unroll
        for (int i = 0; i < 5; i++) {
            float scr = ssc[r0 + i];
            float lsum = 0.f;
#pragma unroll
            for (int j = 0; j < 5; j++) {
                float2 f = u2f(acc[i][j]);
                f.x = __expf(scr * f.x);
                f.y = __expf(scr * f.y);
                lsum += f.x + f.y;
                acc[i][j] = packf2(f.x, f.y);
            }
            atomicAdd(&rsum[r0 + i], lsum);
        }
    }
    __syncthreads();   // rsum complete
    __half* relh = g_relh + (size_t)b * 16900;
    if (tid < 338) {
#pragma unroll
        for (int i = 0; i < 5; i++) {
            float inv = 1.f / rsum[r0 + i];
#pragma unroll
            for (int j = 0; j < 5; j++) {
                float2 f = u2f(acc[i][j]);
                float a0 = fmaxf(f.x * inv - thr, 0.f);
                float a1 = fmaxf(f.y * inv - thr, 0.f);
                __half2 h2 = __floats2half2_rn(a0, a1);
                *(__half2*)(Ah + (r0 + i) * 130 + s0 + 2 * j) = h2;
                *(__half2*)(relh + (r0 + i) * 130 + s0 + 2 * j) = h2;
            }
        }
    }
    __syncthreads();
    if (tid < 130) {
        const int rr = (tid >> 1) * 2, cg = tid & 1;
        const float* yb = ys + cg * 8;
        ULL az[2][4];
#pragma unroll
        for (int i = 0; i < 2; i++)
#pragma unroll
            for (int j = 0; j < 4; j++) az[i][j] = 0ull;
        for (int sp = 0; sp < 65; sp++) {
            float2 af0 = __half22float2(*(const __half2*)(Ah + rr * 130 + 2 * sp));
            float2 af1 = __half22float2(*(const __half2*)(Ah + (rr + 1) * 130 + 2 * sp));
            ulonglong2 p0 = *(const ulonglong2*)(yb + (2 * sp) * 16);
            ulonglong2 p1 = *(const ulonglong2*)(yb + (2 * sp) * 16 + 4);
            ulonglong2 q0 = *(const ulonglong2*)(yb + (2 * sp + 1) * 16);
            ulonglong2 q1 = *(const ulonglong2*)(yb + (2 * sp + 1) * 16 + 4);
            ULL a0 = pack2(af0.x), a1 = pack2(af0.y);
            ffma2(az[0][0], a0, p0.x); ffma2(az[0][1], a0, p0.y);
            ffma2(az[0][2], a0, p1.x); ffma2(az[0][3], a0, p1.y);
            ffma2(az[0][0], a1, q0.x); ffma2(az[0][1], a1, q0.y);
            ffma2(az[0][2], a1, q1.x); ffma2(az[0][3], a1, q1.y);
            ULL b0 = pack2(af1.x), b1 = pack2(af1.y);
            ffma2(az[1][0], b0, p0.x); ffma2(az[1][1], b0, p0.y);
            ffma2(az[1][2], b0, p1.x); ffma2(az[1][3], b0, p1.y);
            ffma2(az[1][0], b1, q0.x); ffma2(az[1][1], b1, q0.y);
            ffma2(az[1][2], b1, q1.x); ffma2(az[1][3], b1, q1.y);
        }
#pragma unroll
        for (int i = 0; i < 2; i++) {
            int r = rr + i;
            float2 f0 = u2f(az[i][0]), f1 = u2f(az[i][1]);
            float2 f2 = u2f(az[i][2]), f3 = u2f(az[i][3]);
            float* zp = g_z + (size_t)b * 2080 + r * 16 + cg * 8;
            *(float4*)zp = make_float4(f0.x, f0.y, f1.x, f1.y);
            *(float4*)(zp + 4) = make_float4(f2.x, f2.y, f3.x, f3.y);
            float s1 = f0.x + f0.y + f1.x + f1.y + f2.x + f2.y + f3.x + f3.y;
            float s2 = f0.x * f0.x + f0.y * f0.y + f1.x * f1.x + f1.y * f1.y
                     + f2.x * f2.x + f2.y * f2.y + f3.x * f3.x + f3.y * f3.y;
            atomicAdd(&ssum[r], s1);
            atomicAdd(&ssq[r], s2);
        }
    }
    __syncthreads();
    if (tid < 130) {
        atomicAdd(&g_stats[1][0][tid], ssum[tid]);
        atomicAdd(&g_stats[1][1][tid], ssq[tid]);
    }
}

// h = relu(bn_{SLOT-1}(z)) [+res]; g_h = h; y = h@w^T+b; z = A@y; stats[SLOT]
template <int FIN, int FOUT, bool RES, int SLOT>
__global__ void __launch_bounds__(256) k_layer(const float* __restrict__ w,
        const float* __restrict__ bias, const float* __restrict__ gam,
        const float* __restrict__ bet, float cinv) {
    extern __shared__ float sm[];
    float* hs = sm;                                      // 130*FIN
    float* ys = sm + 130 * FIN;                          // 130*FOUT
    __half* Ah = (__half*)(sm + 130 * FIN + 130 * FOUT); // 130*130 halves (+pad)
    __shared__ float ws[FOUT * FIN], bs_[FOUT];
    __shared__ float2 sss[130];
    __shared__ float ssum[130], ssq[130];
    const int b = blockIdx.x, tid = threadIdx.x;
    const __half* relh = g_relh + (size_t)b * 16900;
    for (int i = tid; i < 4225; i += 256)
        cpa8(Ah + i * 4, relh + i * 4);
    if (tid < FOUT * FIN) ws[tid] = w[tid];
    if (tid < FOUT) bs_[tid] = bias[tid];
    if (tid < 130) {
        float m = g_stats[SLOT - 1][0][tid] * cinv;
        float v = g_stats[SLOT - 1][1][tid] * cinv - m * m;
        float sc = gam[tid] * rsqrtf(v + 1e-5f);
        sss[tid] = make_float2(sc, bet[tid] - sc * m);
        ssum[tid] = 0.f; ssq[tid] = 0.f;
    }
    __syncthreads();
    const size_t base = (size_t)b * 2080;
    if (FIN == 16) {
        for (int i4 = tid; i4 < 520; i4 += 256) {
            int r = i4 >> 2;
            float2 ss = sss[r];
            float4 z = *(const float4*)(g_z + base + 4 * i4);
            float4 h4;
            h4.x = fmaxf(ss.x * z.x + ss.y, 0.f);
            h4.y = fmaxf(ss.x * z.y + ss.y, 0.f);
            h4.z = fmaxf(ss.x * z.z + ss.y, 0.f);
            h4.w = fmaxf(ss.x * z.w + ss.y, 0.f);
            if (RES) {
                float4 p = *(const float4*)(g_h + base + 4 * i4);
                h4.x += p.x; h4.y += p.y; h4.z += p.z; h4.w += p.w;
            }
            *(float4*)(hs + 4 * i4) = h4;
            *(float4*)(g_h + base + 4 * i4) = h4;
        }
    } else if (FIN == 4) {
        if (tid < 130) {
            float2 ss = sss[tid];
            float4 z = *(const float4*)(g_z + base + tid * 16);
            float4 h4;
            h4.x = fmaxf(ss.x * z.x + ss.y, 0.f);
            h4.y = fmaxf(ss.x * z.y + ss.y, 0.f);
            h4.z = fmaxf(ss.x * z.z + ss.y, 0.f);
            h4.w = fmaxf(ss.x * z.w + ss.y, 0.f);
            if (RES) {
                float4 p = *(const float4*)(g_h + base + tid * 16);
                h4.x += p.x; h4.y += p.y; h4.z += p.z; h4.w += p.w;
            }
            *(float4*)(hs + tid * 4) = h4;
            *(float4*)(g_h + base + tid * 16) = h4;
        }
    } else {  // FIN == 2
        if (tid < 130) {
            float2 ss = sss[tid];
            float2 z = *(const float2*)(g_z + base + tid * 16);
            float2 h2;
            h2.x = fmaxf(ss.x * z.x + ss.y, 0.f);
            h2.y = fmaxf(ss.x * z.y + ss.y, 0.f);
            if (RES) {
                float2 p = *(const float2*)(g_h + base + tid * 16);
                h2.x += p.x; h2.y += p.y;
            }
            *(float2*)(hs + tid * 2) = h2;
            *(float2*)(g_h + base + tid * 16) = h2;
        }
    }
    __syncthreads();
    for (int o = tid; o < 130 * FOUT; o += 256) {
        int r = o / FOUT, fo = o % FOUT;
        float acc = bs_[fo];
#pragma unroll
        for (int f = 0; f < FIN; f++) acc += hs[r * FIN + f] * ws[fo * FIN + f];
        ys[o] = acc;
    }
    cpwait();
    __syncthreads();
    if (FOUT == 16) {
        if (tid < 130) {
            const int rr = (tid >> 1) * 2, cg = tid & 1;
            const float* yb = ys + cg * 8;
            ULL az[2][4];
#pragma unroll
            for (int i = 0; i < 2; i++)
#pragma unroll
                for (int j = 0; j < 4; j++) az[i][j] = 0ull;
            for (int sp = 0; sp < 65; sp++) {
                float2 af0 = __half22float2(*(const __half2*)(Ah + rr * 130 + 2 * sp));
                float2 af1 = __half22float2(*(const __half2*)(Ah + (rr + 1) * 130 + 2 * sp));
                ulonglong2 p0 = *(const ulonglong2*)(yb + (2 * sp) * 16);
                ulonglong2 p1 = *(const ulonglong2*)(yb + (2 * sp) * 16 + 4);
                ulonglong2 q0 = *(const ulonglong2*)(yb + (2 * sp + 1) * 16);
                ulonglong2 q1 = *(const ulonglong2*)(yb + (2 * sp + 1) * 16 + 4);
                ULL a0 = pack2(af0.x), a1 = pack2(af0.y);
                ffma2(az[0][0], a0, p0.x); ffma2(az[0][1], a0, p0.y);
                ffma2(az[0][2], a0, p1.x); ffma2(az[0][3], a0, p1.y);
                ffma2(az[0][0], a1, q0.x); ffma2(az[0][1], a1, q0.y);
                ffma2(az[0][2], a1, q1.x); ffma2(az[0][3], a1, q1.y);
                ULL b0 = pack2(af1.x), b1 = pack2(af1.y);
                ffma2(az[1][0], b0, p0.x); ffma2(az[1][1], b0, p0.y);
                ffma2(az[1][2], b0, p1.x); ffma2(az[1][3], b0, p1.y);
                ffma2(az[1][0], b1, q0.x); ffma2(az[1][1], b1, q0.y);
                ffma2(az[1][2], b1, q1.x); ffma2(az[1][3], b1, q1.y);
            }
#pragma unroll
            for (int i = 0; i < 2; i++) {
                int r = rr + i;
                float2 f0 = u2f(az[i][0]), f1 = u2f(az[i][1]);
                float2 f2 = u2f(az[i][2]), f3 = u2f(az[i][3]);
                float* zp = g_z + base + r * 16 + cg * 8;
                *(float4*)zp = make_float4(f0.x, f0.y, f1.x, f1.y);
                *(float4*)(zp + 4) = make_float4(f2.x, f2.y, f3.x, f3.y);
                float s1 = f0.x + f0.y + f1.x + f1.y + f2.x + f2.y + f3.x + f3.y;
                float s2 = f0.x * f0.x + f0.y * f0.y + f1.x * f1.x + f1.y * f1.y
                         + f2.x * f2.x + f2.y * f2.y + f3.x * f3.x + f3.y * f3.y;
                atomicAdd(&ssum[r], s1);
                atomicAdd(&ssq[r], s2);
            }
        }
    } else if (FOUT == 4) {
        if (tid < 65) {
            const int rr = tid * 2;
            ULL az[2][2];
#pragma unroll
            for (int i = 0; i < 2; i++) { az[i][0] = 0ull; az[i][1] = 0ull; }
            for (int sp = 0; sp < 65; sp++) {
                float2 af0 = __half22float2(*(const __half2*)(Ah + rr * 130 + 2 * sp));
                float2 af1 = __half22float2(*(const __half2*)(Ah + (rr + 1) * 130 + 2 * sp));
                ulonglong2 y0 = *(const ulonglong2*)(ys + (2 * sp) * 4);
                ulonglong2 y1 = *(const ulonglong2*)(ys + (2 * sp + 1) * 4);
                ULL a0 = pack2(af0.x), a1 = pack2(af0.y);
                ffma2(az[0][0], a0, y0.x); ffma2(az[0][1], a0, y0.y);
                ffma2(az[0][0], a1, y1.x); ffma2(az[0][1], a1, y1.y);
                ULL b0 = pack2(af1.x), b1 = pack2(af1.y);
                ffma2(az[1][0], b0, y0.x); ffma2(az[1][1], b0, y0.y);
                ffma2(az[1][0], b1, y1.x); ffma2(az[1][1], b1, y1.y);
            }
#pragma unroll
            for (int i = 0; i < 2; i++) {
                int r = rr + i;
                float2 f0 = u2f(az[i][0]), f1 = u2f(az[i][1]);
                *(float4*)(g_z + base + r * 16) = make_float4(f0.x, f0.y, f1.x, f1.y);
                ssum[r] = f0.x + f0.y + f1.x + f1.y;
                ssq[r] = f0.x * f0.x + f0.y * f0.y + f1.x * f1.x + f1.y * f1.y;
            }
        }
    } else {  // FOUT == 2
        if (tid < 65) {
            const int rr = tid * 2;
            ULL az[2];
            az[0] = 0ull; az[1] = 0ull;
            for (int sp = 0; sp < 65; sp++) {
                float2 af0 = __half22float2(*(const __half2*)(Ah + rr * 130 + 2 * sp));
                float2 af1 = __half22float2(*(const __half2*)(Ah + (rr + 1) * 130 + 2 * sp));
                ULL y0 = *(const ULL*)(ys + (2 * sp) * 2);
                ULL y1 = *(const ULL*)(ys + (2 * sp + 1) * 2);
                ffma2(az[0], pack2(af0.x), y0);
                ffma2(az[0], pack2(af0.y), y1);
                ffma2(az[1], pack2(af1.x), y0);
                ffma2(az[1], pack2(af1.y), y1);
            }
#pragma unroll
            for (int i = 0; i < 2; i++) {
                int r = rr + i;
                float2 f0 = u2f(az[i]);
                *(float2*)(g_z + base + r * 16) = f0;
                ssum[r] = f0.x + f0.y;
                ssq[r] = f0.x * f0.x + f0.y * f0.y;
            }
        }
    }
    __syncthreads();
    if (tid < 130) {
        atomicAdd(&g_stats[SLOT][0][tid], ssum[tid]);
        atomicAdd(&g_stats[SLOT][1][tid], ssq[tid]);
    }
}

// h6 = relu(bn6(z6)) + h5; out = relu(flat(h6) @ w_mlp^T + b_mlp)
__global__ void __launch_bounds__(128) k_mlp(const float* __restrict__ wm,
        const float* __restrict__ bm, float* __restrict__ out,
        const float* __restrict__ gam, const float* __restrict__ bet) {
    __shared__ float red[2][4];
    const int b = blockIdx.x, tid = threadIdx.x;
    const float cinv = 1.f / 8192.f;
    float a0 = 0.f, a1 = 0.f;
    for (int i = tid; i < 260; i += 128) {
        int r = i >> 1, f = i & 1;
        float m = g_stats[6][0][r] * cinv;
        float v = g_stats[6][1][r] * cinv - m * m;
        float sc = gam[r] * rsqrtf(v + 1e-5f);
        float sh = bet[r] - sc * m;
        size_t gi = (size_t)b * 2080 + r * 16 + f;
        float hv = fmaxf(sc * g_z[gi] + sh, 0.f) + g_h[gi];
        a0 += hv * wm[i];
        a1 += hv * wm[260 + i];
    }
#pragma unroll
    for (int o = 16; o; o >>= 1) {
        a0 += __shfl_xor_sync(~0u, a0, o);
        a1 += __shfl_xor_sync(~0u, a1, o);
    }
    if ((tid & 31) == 0) { red[0][tid >> 5] = a0; red[1][tid >> 5] = a1; }
    __syncthreads();
    if (tid == 0) {
        float r0 = red[0][0] + red[0][1] + red[0][2] + red[0][3];
        float r1 = red[1][0] + red[1][1] + red[1][2] + red[1][3];
        out[b * 2 + 0] = fmaxf(r0 + bm[0], 0.f);
        out[b * 2 + 1] = fmaxf(r1 + bm[1], 0.f);
    }
}

extern "C" void kernel_launch(void* const* d_in, const int* in_sizes, int n_in,
                              void* d_out, int out_size) {
    (void)in_sizes; (void)n_in; (void)out_size;
    const float* X   = (const float*)d_in[0];
    const float* thr = (const float*)d_in[1];
    const float* wq  = (const float*)d_in[2];
    const float* bq  = (const float*)d_in[3];
    const float* g_t = (const float*)d_in[4];
    const float *w1 = (const float*)d_in[6],  *b1 = (const float*)d_in[7];
    const float *g1 = (const float*)d_in[8],  *e1 = (const float*)d_in[9];
    const float *w2 = (const float*)d_in[10], *b2 = (const float*)d_in[11];
    const float *g2 = (const float*)d_in[12], *e2 = (const float*)d_in[13];
    const float *w3 = (const float*)d_in[14], *b3 = (const float*)d_in[15];
    const float *g3 = (const float*)d_in[16], *e3 = (const float*)d_in[17];
    const float *w4 = (const float*)d_in[18], *b4 = (const float*)d_in[19];
    const float *g4 = (const float*)d_in[20], *e4 = (const float*)d_in[21];
    const float *w5 = (const float*)d_in[22], *b5 = (const float*)d_in[23];
    const float *g5 = (const float*)d_in[24], *e5 = (const float*)d_in[25];
    const float *w6 = (const float*)d_in[26], *b6 = (const float*)d_in[27];
    const float *g6 = (const float*)d_in[28], *e6 = (const float*)d_in[29];
    const float *wm = (const float*)d_in[30], *bm = (const float*)d_in[31];

    const int sm0  = (128 * 102 + 80 * 102) * 4;
    const int smA  = (8580 + 8448) * 4;                     // 68112
    const int smL2 = (2080 + 2080) * 4 + 17160 * 2;
    const int smL3 = (2080 + 520) * 4 + 17160 * 2;
    const int smL4 = (520 + 520) * 4 + 17160 * 2;
    const int smL5 = (520 + 260) * 4 + 17160 * 2;
    const int smL6 = (260 + 260) * 4 + 17160 * 2;
    cudaFuncSetAttribute(k_gemm0, cudaFuncAttributeMaxDynamicSharedMemorySize, sm0);
    cudaFuncSetAttribute(k_adjL1, cudaFuncAttributeMaxDynamicSharedMemorySize, smA);
    cudaFuncSetAttribute(k_layer<16,16,false,2>, cudaFuncAttributeMaxDynamicSharedMemorySize, smL2);
    cudaFuncSetAttribute(k_layer<16,4,true,3>,  cudaFuncAttributeMaxDynamicSharedMemorySize, smL3);
    cudaFuncSetAttribute(k_layer<4,4,false,4>,  cudaFuncAttributeMaxDynamicSharedMemorySize, smL4);
    cudaFuncSetAttribute(k_layer<4,2,true,5>,   cudaFuncAttributeMaxDynamicSharedMemorySize, smL5);
    cudaFuncSetAttribute(k_layer<2,2,false,6>,  cudaFuncAttributeMaxDynamicSharedMemorySize, smL6);

    k_zero<<<1, 256>>>();
    k_gemm0<<<4160, 256, sm0>>>(X, wq, bq, w1, b1);
    k_rel<<<4096, 352>>>();
    k_adjL1<<<4096, 352, smA>>>(thr, g_t);
    k_layer<16,16,false,2><<<4096, 256, smL2>>>(w2, b2, g1, e1, 1.f / 65536.f);
    k_layer<16,4,true,3><<<4096, 256, smL3>>>(w3, b3, g2, e2, 1.f / 65536.f);
    k_layer<4,4,false,4><<<4096, 256, smL4>>>(w4, b4, g3, e3, 1.f / 16384.f);
    k_layer<4,2,true,5><<<4096, 256, smL5>>>(w5, b5, g4, e4, 1.f / 16384.f);
    k_layer<2,2,false,6><<<4096, 256, smL6>>>(w6, b6, g5, e5, 1.f / 8192.f);
    k_mlp<<<4096, 128>>>(wm, bm, (float*)d_out, g6, e6);
}

// round 15
// speedup vs baseline: 1.9901x; 1.0414x over previous
#include <cuda_runtime.h>
#include <cuda_fp16.h>
#include <cstdint>
#include <math.h>

typedef unsigned long long ULL;

// B=4096 R=130 T=200 Q=64
__device__ float g_qky[(size_t)4096 * 130 * 80];    // qk(64) | y1(16), stride 80
__device__ __half g_relh[(size_t)4096 * 130 * 130]; // raw rel fp16 -> A fp16 (in place)
__device__ float g_z[(size_t)4096 * 130 * 16];      // pre-BN z (stride 16)
__device__ float g_h[(size_t)4096 * 130 * 16];      // h_i (stride 16)
__device__ float g_stats[7][2][130];                // (sum, sumsq) per channel

__device__ __forceinline__ void ffma2(ULL& d, ULL a, ULL b) {
    asm("fma.rn.f32x2 %0, %1, %2, %0;" : "+l"(d) : "l"(a), "l"(b));
}
__device__ __forceinline__ ULL pack2(float v) {
    ULL r; asm("mov.b64 %0, {%1, %1};" : "=l"(r) : "f"(v)); return r;
}
__device__ __forceinline__ float2 u2f(ULL u) {
    float2 f; asm("mov.b64 {%0, %1}, %2;" : "=f"(f.x), "=f"(f.y) : "l"(u)); return f;
}
__device__ __forceinline__ void cpa8(void* dst, const void* src) {
    unsigned d = (unsigned)__cvta_generic_to_shared(dst);
    asm volatile("cp.async.ca.shared.global [%0], [%1], 8;" :: "r"(d), "l"(src));
}
__device__ __forceinline__ void cpwait() {
    asm volatile("cp.async.wait_all;" ::: "memory");
}

__global__ void k_zero() {
    float* p = &g_stats[0][0][0];
    for (int i = threadIdx.x; i < 7 * 2 * 130; i += 256) p[i] = 0.f;
}

// C[m,n] = sum_t clean(X)[m,t] * W[n,t] + bias   (W=[wq;w1], M=B*R, N=80, K=200)
__global__ void __launch_bounds__(256) k_gemm0(const float* __restrict__ X,
        const float* __restrict__ wq, const float* __restrict__ bq,
        const float* __restrict__ w1, const float* __restrict__ b1) {
    extern __shared__ float sm[];
    float* Xs = sm;                // 128 x 102
    float* Ws = sm + 128 * 102;    // 80 x 102
    const int tid = threadIdx.x;
    const int tx = tid & 15, ty = tid >> 4;
    const size_t m0 = (size_t)blockIdx.x * 128;
    ULL acc[8][5];
#pragma unroll
    for (int i = 0; i < 8; i++)
#pragma unroll
        for (int j = 0; j < 5; j++) acc[i][j] = 0ull;

    for (int kc = 0; kc < 2; kc++) {
        for (int i = tid; i < 128 * 50; i += 256) {
            int r = i / 50, c = (i % 50) * 2;
            float2 v = *(const float2*)(X + (m0 + r) * 200 + kc * 100 + c);
            if (!(v.x == v.x)) v.x = 0.f;
            if (!(v.y == v.y)) v.y = 0.f;
            *(float2*)(Xs + r * 102 + c) = v;
        }
        for (int i = tid; i < 80 * 50; i += 256) {
            int r = i / 50, c = (i % 50) * 2;
            const float* src = (r < 64) ? wq + r * 200 : w1 + (r - 64) * 200;
            *(float2*)(Ws + r * 102 + c) = *(const float2*)(src + kc * 100 + c);
        }
        __syncthreads();
#pragma unroll 5
        for (int kk = 0; kk < 50; kk++) {
            ULL xv[8], wv[5];
#pragma unroll
            for (int i = 0; i < 8; i++)
                xv[i] = *(const ULL*)(Xs + (ty * 8 + i) * 102 + 2 * kk);
#pragma unroll
            for (int j = 0; j < 5; j++)
                wv[j] = *(const ULL*)(Ws + (tx * 5 + j) * 102 + 2 * kk);
#pragma unroll
            for (int i = 0; i < 8; i++)
#pragma unroll
                for (int j = 0; j < 5; j++) ffma2(acc[i][j], xv[i], wv[j]);
        }
        __syncthreads();
    }
#pragma unroll
    for (int j = 0; j < 5; j++) {
        int n = tx * 5 + j;
        float bias = (n < 64) ? bq[n] : b1[n - 64];
#pragma unroll
        for (int i = 0; i < 8; i++) {
            float2 f = u2f(acc[i][j]);
            g_qky[(m0 + ty * 8 + i) * 80 + n] = f.x + f.y + bias;
        }
    }
}

// rel[b,r,s] = sum_q qk[b,r,q]*flat[b,q*130+s]; write fp16 rel; BN0 stats (fp32)
__global__ void __launch_bounds__(352) k_rel() {
    __shared__ float ba[130 * 64];     // qk row-major
    __shared__ float bk[64 * 132];     // flat reshaped, padded
    __shared__ float ssum[130], ssq[130];
    const int b = blockIdx.x, tid = threadIdx.x;
    const float* qk = g_qky + (size_t)b * 10400;
    __half* relh = g_relh + (size_t)b * 16900;
    for (int f = tid; f < 8320; f += 352) {
        float v = qk[(f >> 6) * 80 + (f & 63)];
        ba[f] = v;
        bk[(f / 130) * 132 + (f % 130)] = v;
    }
    if (tid < 130) { ssum[tid] = 0.f; ssq[tid] = 0.f; }
    __syncthreads();
    if (tid < 338) {
        const int tr = tid / 13, ts = tid - tr * 13;
        const int r0 = tr * 5, s0 = ts * 10;
        ULL acc[5][5];
#pragma unroll
        for (int i = 0; i < 5; i++)
#pragma unroll
            for (int j = 0; j < 5; j++) acc[i][j] = 0ull;
        for (int q = 0; q < 64; q++) {
            ULL kv[5];
#pragma unroll
            for (int j = 0; j < 5; j++) kv[j] = *(const ULL*)(bk + q * 132 + s0 + 2 * j);
#pragma unroll
            for (int i = 0; i < 5; i++) {
                ULL ap = pack2(ba[(r0 + i) * 64 + q]);
#pragma unroll
                for (int j = 0; j < 5; j++) ffma2(acc[i][j], ap, kv[j]);
            }
        }
#pragma unroll
        for (int i = 0; i < 5; i++) {
            float s = 0.f, s2 = 0.f;
#pragma unroll
            for (int j = 0; j < 5; j++) {
                float2 f = u2f(acc[i][j]);
                *(__half2*)(relh + (r0 + i) * 130 + s0 + 2 * j) = __floats2half2_rn(f.x, f.y);
                s += f.x + f.y; s2 += f.x * f.x + f.y * f.y;
            }
            atomicAdd(&ssum[r0 + i], s);
            atomicAdd(&ssq[r0 + i], s2);
        }
    }
    __syncthreads();
    if (tid < 130) {
        atomicAdd(&g_stats[0][0][tid], ssum[tid]);
        atomicAdd(&g_stats[0][1][tid], ssq[tid]);
    }
}

// Read fp16 rel; softmax(sc*rel) (shift cancels); relu(-thr) -> A fp16 in place;
// z1 = A @ y1; BN1 stats.
__global__ void __launch_bounds__(256, 4) k_adjL1(const float* __restrict__ thr_p,
        const float* __restrict__ gam) {
    extern __shared__ char smraw[];
    __half* Ah = (__half*)smraw;                 // 16900 halves (region padded to 33808B)
    float* ys = (float*)(smraw + 33808);         // 2080 floats
    __shared__ float ssc[130], ssum[130], ssq[130];
    const int b = blockIdx.x, tid = threadIdx.x;
    const float thr = *thr_p;
    const float* qk = g_qky + (size_t)b * 10400;
    __half* relh = g_relh + (size_t)b * 16900;
    if (tid < 130) {
        const float cinv = 1.f / 532480.f;
        float m = g_stats[0][0][tid] * cinv;
        float va = g_stats[0][1][tid] * cinv - m * m;
        ssc[tid] = gam[tid] * rsqrtf(va + 1e-5f);
        ssum[tid] = 0.f; ssq[tid] = 0.f;
    }
    for (int i = tid; i < 2080; i += 256)
        ys[i] = qk[(i >> 4) * 80 + 64 + (i & 15)];
    __syncthreads();
    const int w = tid >> 5, lane = tid & 31;
    for (int r = w; r < 130; r += 8) {
        float sc = ssc[r];
        float v[5];
        float mx = -1e30f;
#pragma unroll
        for (int k = 0; k < 5; k++) {
            int s = lane + 32 * k;
            v[k] = (s < 130) ? sc * __half2float(relh[r * 130 + s]) : -1e30f;
            mx = fmaxf(mx, v[k]);
        }
#pragma unroll
        for (int o = 16; o; o >>= 1) mx = fmaxf(mx, __shfl_xor_sync(~0u, mx, o));
        float e[5], sum = 0.f;
#pragma unroll
        for (int k = 0; k < 5; k++) {
            int s = lane + 32 * k;
            e[k] = (s < 130) ? __expf(v[k] - mx) : 0.f;
            sum += e[k];
        }
#pragma unroll
        for (int o = 16; o; o >>= 1) sum += __shfl_xor_sync(~0u, sum, o);
        float inv = 1.f / sum;
#pragma unroll
        for (int k = 0; k < 5; k++) {
            int s = lane + 32 * k;
            if (s < 130) {
                __half a = __float2half(fmaxf(e[k] * inv - thr, 0.f));
                Ah[r * 130 + s] = a;
                relh[r * 130 + s] = a;
            }
        }
    }
    __syncthreads();
    if (tid < 130) {
        const int rr = (tid >> 1) * 2, cg = tid & 1;
        const float* yb = ys + cg * 8;
        ULL az[2][4];
#pragma unroll
        for (int i = 0; i < 2; i++)
#pragma unroll
            for (int j = 0; j < 4; j++) az[i][j] = 0ull;
        for (int sp = 0; sp < 65; sp++) {
            float2 af0 = __half22float2(*(const __half2*)(Ah + rr * 130 + 2 * sp));
            float2 af1 = __half22float2(*(const __half2*)(Ah + (rr + 1) * 130 + 2 * sp));
            ulonglong2 p0 = *(const ulonglong2*)(yb + (2 * sp) * 16);
            ulonglong2 p1 = *(const ulonglong2*)(yb + (2 * sp) * 16 + 4);
            ulonglong2 q0 = *(const ulonglong2*)(yb + (2 * sp + 1) * 16);
            ulonglong2 q1 = *(const ulonglong2*)(yb + (2 * sp + 1) * 16 + 4);
            ULL a0 = pack2(af0.x), a1 = pack2(af0.y);
            ffma2(az[0][0], a0, p0.x); ffma2(az[0][1], a0, p0.y);
            ffma2(az[0][2], a0, p1.x); ffma2(az[0][3], a0, p1.y);
            ffma2(az[0][0], a1, q0.x); ffma2(az[0][1], a1, q0.y);
            ffma2(az[0][2], a1, q1.x); ffma2(az[0][3], a1, q1.y);
            ULL b0 = pack2(af1.x), b1 = pack2(af1.y);
            ffma2(az[1][0], b0, p0.x); ffma2(az[1][1], b0, p0.y);
            ffma2(az[1][2], b0, p1.x); ffma2(az[1][3], b0, p1.y);
            ffma2(az[1][0], b1, q0.x); ffma2(az[1][1], b1, q0.y);
            ffma2(az[1][2], b1, q1.x); ffma2(az[1][3], b1, q1.y);
        }
#pragma unroll
        for (int i = 0; i < 2; i++) {
            int r = rr + i;
            float2 f0 = u2f(az[i][0]), f1 = u2f(az[i][1]);
            float2 f2 = u2f(az[i][2]), f3 = u2f(az[i][3]);
            float* zp = g_z + (size_t)b * 2080 + r * 16 + cg * 8;
            *(float4*)zp = make_float4(f0.x, f0.y, f1.x, f1.y);
            *(float4*)(zp + 4) = make_float4(f2.x, f2.y, f3.x, f3.y);
            float s1 = f0.x + f0.y + f1.x + f1.y + f2.x + f2.y + f3.x + f3.y;
            float s2 = f0.x * f0.x + f0.y * f0.y + f1.x * f1.x + f1.y * f1.y
                     + f2.x * f2.x + f2.y * f2.y + f3.x * f3.x + f3.y * f3.y;
            atomicAdd(&ssum[r], s1);
            atomicAdd(&ssq[r], s2);
        }
    }
    __syncthreads();
    if (tid < 130) {
        atomicAdd(&g_stats[1][0][tid], ssum[tid]);
        atomicAdd(&g_stats[1][1][tid], ssq[tid]);
    }
}

// h = relu(bn_{SLOT-1}(z)) [+res]; g_h = h; y = h@w^T+b; z = A@y; stats[SLOT]
template <int FIN, int FOUT, bool RES, int SLOT>
__global__ void __launch_bounds__(256) k_layer(const float* __restrict__ w,
        const float* __restrict__ bias, const float* __restrict__ gam,
        const float* __restrict__ bet, float cinv) {
    extern __shared__ float sm[];
    float* hs = sm;                                      // 130*FIN
    float* ys = sm + 130 * FIN;                          // 130*FOUT
    __half* Ah = (__half*)(sm + 130 * FIN + 130 * FOUT); // 130*130 halves (+pad)
    __shared__ float ws[FOUT * FIN], bs_[FOUT];
    __shared__ float2 sss[130];
    __shared__ float ssum[130], ssq[130];
    const int b = blockIdx.x, tid = threadIdx.x;
    const __half* relh = g_relh + (size_t)b * 16900;
    for (int i = tid; i < 4225; i += 256)
        cpa8(Ah + i * 4, relh + i * 4);
    if (tid < FOUT * FIN) ws[tid] = w[tid];
    if (tid < FOUT) bs_[tid] = bias[tid];
    if (tid < 130) {
        float m = g_stats[SLOT - 1][0][tid] * cinv;
        float v = g_stats[SLOT - 1][1][tid] * cinv - m * m;
        float sc = gam[tid] * rsqrtf(v + 1e-5f);
        sss[tid] = make_float2(sc, bet[tid] - sc * m);
        ssum[tid] = 0.f; ssq[tid] = 0.f;
    }
    __syncthreads();
    const size_t base = (size_t)b * 2080;
    if (FIN == 16) {
        for (int i4 = tid; i4 < 520; i4 += 256) {
            int r = i4 >> 2;
            float2 ss = sss[r];
            float4 z = *(const float4*)(g_z + base + 4 * i4);
            float4 h4;
            h4.x = fmaxf(ss.x * z.x + ss.y, 0.f);
            h4.y = fmaxf(ss.x * z.y + ss.y, 0.f);
            h4.z = fmaxf(ss.x * z.z + ss.y, 0.f);
            h4.w = fmaxf(ss.x * z.w + ss.y, 0.f);
            if (RES) {
                float4 p = *(const float4*)(g_h + base + 4 * i4);
                h4.x += p.x; h4.y += p.y; h4.z += p.z; h4.w += p.w;
            }
            *(float4*)(hs + 4 * i4) = h4;
            *(float4*)(g_h + base + 4 * i4) = h4;
        }
    } else if (FIN == 4) {
        if (tid < 130) {
            float2 ss = sss[tid];
            float4 z = *(const float4*)(g_z + base + tid * 16);
            float4 h4;
            h4.x = fmaxf(ss.x * z.x + ss.y, 0.f);
            h4.y = fmaxf(ss.x * z.y + ss.y, 0.f);
            h4.z = fmaxf(ss.x * z.z + ss.y, 0.f);
            h4.w = fmaxf(ss.x * z.w + ss.y, 0.f);
            if (RES) {
                float4 p = *(const float4*)(g_h + base + tid * 16);
                h4.x += p.x; h4.y += p.y; h4.z += p.z; h4.w += p.w;
            }
            *(float4*)(hs + tid * 4) = h4;
            *(float4*)(g_h + base + tid * 16) = h4;
        }
    } else {  // FIN == 2
        if (tid < 130) {
            float2 ss = sss[tid];
            float2 z = *(const float2*)(g_z + base + tid * 16);
            float2 h2;
            h2.x = fmaxf(ss.x * z.x + ss.y, 0.f);
            h2.y = fmaxf(ss.x * z.y + ss.y, 0.f);
            if (RES) {
                float2 p = *(const float2*)(g_h + base + tid * 16);
                h2.x += p.x; h2.y += p.y;
            }
            *(float2*)(hs + tid * 2) = h2;
            *(float2*)(g_h + base + tid * 16) = h2;
        }
    }
    __syncthreads();
    for (int o = tid; o < 130 * FOUT; o += 256) {
        int r = o / FOUT, fo = o % FOUT;
        float acc = bs_[fo];
#pragma unroll
        for (int f = 0; f < FIN; f++) acc += hs[r * FIN + f] * ws[fo * FIN + f];
        ys[o] = acc;
    }
    cpwait();
    __syncthreads();
    if (FOUT == 16) {
        if (tid < 130) {
            const int rr = (tid >> 1) * 2, cg = tid & 1;
            const float* yb = ys + cg * 8;
            ULL az[2][4];
#pragma unroll
            for (int i = 0; i < 2; i++)
#pragma unroll
                for (int j = 0; j < 4; j++) az[i][j] = 0ull;
            for (int sp = 0; sp < 65; sp++) {
                float2 af0 = __half22float2(*(const __half2*)(Ah + rr * 130 + 2 * sp));
                float2 af1 = __half22float2(*(const __half2*)(Ah + (rr + 1) * 130 + 2 * sp));
                ulonglong2 p0 = *(const ulonglong2*)(yb + (2 * sp) * 16);
                ulonglong2 p1 = *(const ulonglong2*)(yb + (2 * sp) * 16 + 4);
                ulonglong2 q0 = *(const ulonglong2*)(yb + (2 * sp + 1) * 16);
                ulonglong2 q1 = *(const ulonglong2*)(yb + (2 * sp + 1) * 16 + 4);
                ULL a0 = pack2(af0.x), a1 = pack2(af0.y);
                ffma2(az[0][0], a0, p0.x); ffma2(az[0][1], a0, p0.y);
                ffma2(az[0][2], a0, p1.x); ffma2(az[0][3], a0, p1.y);
                ffma2(az[0][0], a1, q0.x); ffma2(az[0][1], a1, q0.y);
                ffma2(az[0][2], a1, q1.x); ffma2(az[0][3], a1, q1.y);
                ULL b0 = pack2(af1.x), b1 = pack2(af1.y);
                ffma2(az[1][0], b0, p0.x); ffma2(az[1][1], b0, p0.y);
                ffma2(az[1][2], b0, p1.x); ffma2(az[1][3], b0, p1.y);
                ffma2(az[1][0], b1, q0.x); ffma2(az[1][1], b1, q0.y);
                ffma2(az[1][2], b1, q1.x); ffma2(az[1][3], b1, q1.y);
            }
#pragma unroll
            for (int i = 0; i < 2; i++) {
                int r = rr + i;
                float2 f0 = u2f(az[i][0]), f1 = u2f(az[i][1]);
                float2 f2 = u2f(az[i][2]), f3 = u2f(az[i][3]);
                float* zp = g_z + base + r * 16 + cg * 8;
                *(float4*)zp = make_float4(f0.x, f0.y, f1.x, f1.y);
                *(float4*)(zp + 4) = make_float4(f2.x, f2.y, f3.x, f3.y);
                float s1 = f0.x + f0.y + f1.x + f1.y + f2.x + f2.y + f3.x + f3.y;
                float s2 = f0.x * f0.x + f0.y * f0.y + f1.x * f1.x + f1.y * f1.y
                         + f2.x * f2.x + f2.y * f2.y + f3.x * f3.x + f3.y * f3.y;
                atomicAdd(&ssum[r], s1);
                atomicAdd(&ssq[r], s2);
            }
        }
    } else if (FOUT == 4) {
        if (tid < 65) {
            const int rr = tid * 2;
            ULL az[2][2];
#pragma unroll
            for (int i = 0; i < 2; i++) { az[i][0] = 0ull; az[i][1] = 0ull; }
            for (int sp = 0; sp < 65; sp++) {
                float2 af0 = __half22float2(*(const __half2*)(Ah + rr * 130 + 2 * sp));
                float2 af1 = __half22float2(*(const __half2*)(Ah + (rr + 1) * 130 + 2 * sp));
                ulonglong2 y0 = *(const ulonglong2*)(ys + (2 * sp) * 4);
                ulonglong2 y1 = *(const ulonglong2*)(ys + (2 * sp + 1) * 4);
                ULL a0 = pack2(af0.x), a1 = pack2(af0.y);
                ffma2(az[0][0], a0, y0.x); ffma2(az[0][1], a0, y0.y);
                ffma2(az[0][0], a1, y1.x); ffma2(az[0][1], a1, y1.y);
                ULL b0 = pack2(af1.x), b1 = pack2(af1.y);
                ffma2(az[1][0], b0, y0.x); ffma2(az[1][1], b0, y0.y);
                ffma2(az[1][0], b1, y1.x); ffma2(az[1][1], b1, y1.y);
            }
#pragma unroll
            for (int i = 0; i < 2; i++) {
                int r = rr + i;
                float2 f0 = u2f(az[i][0]), f1 = u2f(az[i][1]);
                *(float4*)(g_z + base + r * 16) = make_float4(f0.x, f0.y, f1.x, f1.y);
                ssum[r] = f0.x + f0.y + f1.x + f1.y;
                ssq[r] = f0.x * f0.x + f0.y * f0.y + f1.x * f1.x + f1.y * f1.y;
            }
        }
    } else {  // FOUT == 2
        if (tid < 65) {
            const int rr = tid * 2;
            ULL az[2];
            az[0] = 0ull; az[1] = 0ull;
            for (int sp = 0; sp < 65; sp++) {
                float2 af0 = __half22float2(*(const __half2*)(Ah + rr * 130 + 2 * sp));
                float2 af1 = __half22float2(*(const __half2*)(Ah + (rr + 1) * 130 + 2 * sp));
                ULL y0 = *(const ULL*)(ys + (2 * sp) * 2);
                ULL y1 = *(const ULL*)(ys + (2 * sp + 1) * 2);
                ffma2(az[0], pack2(af0.x), y0);
                ffma2(az[0], pack2(af0.y), y1);
                ffma2(az[1], pack2(af1.x), y0);
                ffma2(az[1], pack2(af1.y), y1);
            }
#pragma unroll
            for (int i = 0; i < 2; i++) {
                int r = rr + i;
                float2 f0 = u2f(az[i]);
                *(float2*)(g_z + base + r * 16) = f0;
                ssum[r] = f0.x + f0.y;
                ssq[r] = f0.x * f0.x + f0.y * f0.y;
            }
        }
    }
    __syncthreads();
    if (tid < 130) {
        atomicAdd(&g_stats[SLOT][0][tid], ssum[tid]);
        atomicAdd(&g_stats[SLOT][1][tid], ssq[tid]);
    }
}

// h6 = relu(bn6(z6)) + h5; out = relu(flat(h6) @ w_mlp^T + b_mlp)
__global__ void __launch_bounds__(128) k_mlp(const float* __restrict__ wm,
        const float* __restrict__ bm, float* __restrict__ out,
        const float* __restrict__ gam, const float* __restrict__ bet) {
    __shared__ float red[2][4];
    const int b = blockIdx.x, tid = threadIdx.x;
    const float cinv = 1.f / 8192.f;
    float a0 = 0.f, a1 = 0.f;
    for (int i = tid; i < 260; i += 128) {
        int r = i >> 1, f = i & 1;
        float m = g_stats[6][0][r] * cinv;
        float v = g_stats[6][1][r] * cinv - m * m;
        float sc = gam[r] * rsqrtf(v + 1e-5f);
        float sh = bet[r] - sc * m;
        size_t gi = (size_t)b * 2080 + r * 16 + f;
        float hv = fmaxf(sc * g_z[gi] + sh, 0.f) + g_h[gi];
        a0 += hv * wm[i];
        a1 += hv * wm[260 + i];
    }
#pragma unroll
    for (int o = 16; o; o >>= 1) {
        a0 += __shfl_xor_sync(~0u, a0, o);
        a1 += __shfl_xor_sync(~0u, a1, o);
    }
    if ((tid & 31) == 0) { red[0][tid >> 5] = a0; red[1][tid >> 5] = a1; }
    __syncthreads();
    if (tid == 0) {
        float r0 = red[0][0] + red[0][1] + red[0][2] + red[0][3];
        float r1 = red[1][0] + red[1][1] + red[1][2] + red[1][3];
        out[b * 2 + 0] = fmaxf(r0 + bm[0], 0.f);
        out[b * 2 + 1] = fmaxf(r1 + bm[1], 0.f);
    }
}

extern "C" void kernel_launch(void* const* d_in, const int* in_sizes, int n_in,
                              void* d_out, int out_size) {
    (void)in_sizes; (void)n_in; (void)out_size;
    const float* X   = (const float*)d_in[0];
    const float* thr = (const float*)d_in[1];
    const float* wq  = (const float*)d_in[2];
    const float* bq  = (const float*)d_in[3];
    const float* g_t = (const float*)d_in[4];
    const float *w1 = (const float*)d_in[6],  *b1 = (const float*)d_in[7];
    const float *g1 = (const float*)d_in[8],  *e1 = (const float*)d_in[9];
    const float *w2 = (const float*)d_in[10], *b2 = (const float*)d_in[11];
    const float *g2 = (const float*)d_in[12], *e2 = (const float*)d_in[13];
    const float *w3 = (const float*)d_in[14], *b3 = (const float*)d_in[15];
    const float *g3 = (const float*)d_in[16], *e3 = (const float*)d_in[17];
    const float *w4 = (const float*)d_in[18], *b4 = (const float*)d_in[19];
    const float *g4 = (const float*)d_in[20], *e4 = (const float*)d_in[21];
    const float *w5 = (const float*)d_in[22], *b5 = (const float*)d_in[23];
    const float *g5 = (const float*)d_in[24], *e5 = (const float*)d_in[25];
    const float *w6 = (const float*)d_in[26], *b6 = (const float*)d_in[27];
    const float *g6 = (const float*)d_in[28], *e6 = (const float*)d_in[29];
    const float *wm = (const float*)d_in[30], *bm = (const float*)d_in[31];

    const int sm0  = (128 * 102 + 80 * 102) * 4;
    const int smA  = 33808 + 2080 * 4;                      // 42128
    const int smL2 = (2080 + 2080) * 4 + 17160 * 2;
    const int smL3 = (2080 + 520) * 4 + 17160 * 2;
    const int smL4 = (520 + 520) * 4 + 17160 * 2;
    const int smL5 = (520 + 260) * 4 + 17160 * 2;
    const int smL6 = (260 + 260) * 4 + 17160 * 2;
    cudaFuncSetAttribute(k_gemm0, cudaFuncAttributeMaxDynamicSharedMemorySize, sm0);
    cudaFuncSetAttribute(k_adjL1, cudaFuncAttributeMaxDynamicSharedMemorySize, smA);
    cudaFuncSetAttribute(k_layer<16,16,false,2>, cudaFuncAttributeMaxDynamicSharedMemorySize, smL2);
    cudaFuncSetAttribute(k_layer<16,4,true,3>,  cudaFuncAttributeMaxDynamicSharedMemorySize, smL3);
    cudaFuncSetAttribute(k_layer<4,4,false,4>,  cudaFuncAttributeMaxDynamicSharedMemorySize, smL4);
    cudaFuncSetAttribute(k_layer<4,2,true,5>,   cudaFuncAttributeMaxDynamicSharedMemorySize, smL5);
    cudaFuncSetAttribute(k_layer<2,2,false,6>,  cudaFuncAttributeMaxDynamicSharedMemorySize, smL6);

    k_zero<<<1, 256>>>();
    k_gemm0<<<4160, 256, sm0>>>(X, wq, bq, w1, b1);
    k_rel<<<4096, 352>>>();
    k_adjL1<<<4096, 256, smA>>>(thr, g_t);
    k_layer<16,16,false,2><<<4096, 256, smL2>>>(w2, b2, g1, e1, 1.f / 65536.f);
    k_layer<16,4,true,3><<<4096, 256, smL3>>>(w3, b3, g2, e2, 1.f / 65536.f);
    k_layer<4,4,false,4><<<4096, 256, smL4>>>(w4, b4, g3, e3, 1.f / 16384.f);
    k_layer<4,2,true,5><<<4096, 256, smL5>>>(w5, b5, g4, e4, 1.f / 16384.f);
    k_layer<2,2,false,6><<<4096, 256, smL6>>>(w6, b6, g5, e5, 1.f / 8192.f);
    k_mlp<<<4096, 128>>>(wm, bm, (float*)d_out, g6, e6);
}